// round 4
// baseline (speedup 1.0000x reference)
#include <cuda_runtime.h>
#include <cuda_bf16.h>
#include <cstdint>

// ============================================================================
// Problem constants
// ============================================================================
#define B_ROWS 32768
#define D_INF  512
#define D_OUTF 2048
#define VBSZ   256
#define NVB    (B_ROWS / VBSZ)   // 128
#define BN_EPS 1e-5f

// ============================================================================
// Device scratch (static globals; no cudaMalloc allowed)
// ============================================================================
__device__ __nv_bfloat16 g_A0[(size_t)B_ROWS * D_INF];   // hi bf16 of feat
__device__ __nv_bfloat16 g_A1[(size_t)B_ROWS * D_INF];   // lo bf16 of feat
__device__ __nv_bfloat16 g_W0[(size_t)D_OUTF * D_INF];   // hi bf16 of W
__device__ __nv_bfloat16 g_W1[(size_t)D_OUTF * D_INF];   // lo bf16 of W
__device__ float         g_x [(size_t)B_ROWS * D_OUTF];  // GEMM result
__device__ float         g_psum [(size_t)NVB * D_OUTF];  // col sums per vb
__device__ float         g_psum2[(size_t)NVB * D_OUTF];  // col sumsq per vb
__device__ float         g_scale[(size_t)NVB * D_OUTF];  // rstd*gamma
__device__ float         g_shift[(size_t)NVB * D_OUTF];  // beta - mean*rstd*gamma

// ============================================================================
// PTX helpers (base ISA only: cp.async + ldmatrix + mma.sync)
// ============================================================================
__device__ __forceinline__ uint32_t smem_to_u32(const void* p) {
    uint32_t a;
    asm("{ .reg .u64 t; cvta.to.shared.u64 t, %1; cvt.u32.u64 %0, t; }" : "=r"(a) : "l"(p));
    return a;
}

#define CP_ASYNC_16(dst_u32, src_ptr) \
    asm volatile("cp.async.cg.shared.global [%0], [%1], 16;" :: "r"(dst_u32), "l"(src_ptr))
#define CP_ASYNC_COMMIT() asm volatile("cp.async.commit_group;" ::: "memory")
#define CP_ASYNC_WAIT_1() asm volatile("cp.async.wait_group 1;" ::: "memory")

#define LDMATRIX_X4(r0, r1, r2, r3, addr) \
    asm volatile("ldmatrix.sync.aligned.m8n8.x4.shared.b16 {%0,%1,%2,%3}, [%4];" \
                 : "=r"(r0), "=r"(r1), "=r"(r2), "=r"(r3) : "r"(addr))

#define MMA_16816(d, a, b0, b1) \
    asm volatile("mma.sync.aligned.m16n8k16.row.col.f32.bf16.bf16.f32 " \
                 "{%0,%1,%2,%3}, {%4,%5,%6,%7}, {%8,%9}, {%0,%1,%2,%3};" \
                 : "+f"((d)[0]), "+f"((d)[1]), "+f"((d)[2]), "+f"((d)[3]) \
                 : "r"((a)[0]), "r"((a)[1]), "r"((a)[2]), "r"((a)[3]), "r"(b0), "r"(b1))

// ============================================================================
// Kernel 1: split fp32 -> (bf16 hi, bf16 lo) for A (feat) and W
// ============================================================================
__global__ void k_split(const float* __restrict__ feat, const float* __restrict__ Wm) {
    constexpr int NA4 = B_ROWS * D_INF / 4;   // 4194304
    constexpr int NW4 = D_OUTF * D_INF / 4;   // 262144
    int idx = blockIdx.x * blockDim.x + threadIdx.x;
    const float* src;
    __nv_bfloat16 *d0, *d1;
    int i;
    if (idx < NA4) { src = feat; d0 = g_A0; d1 = g_A1; i = idx; }
    else if (idx < NA4 + NW4) { src = Wm; d0 = g_W0; d1 = g_W1; i = idx - NA4; }
    else return;

    float4 a = reinterpret_cast<const float4*>(src)[i];
    __nv_bfloat16 hx = __float2bfloat16(a.x), hy = __float2bfloat16(a.y);
    __nv_bfloat16 hz = __float2bfloat16(a.z), hw = __float2bfloat16(a.w);
    __nv_bfloat16 lx = __float2bfloat16(a.x - __bfloat162float(hx));
    __nv_bfloat16 ly = __float2bfloat16(a.y - __bfloat162float(hy));
    __nv_bfloat16 lz = __float2bfloat16(a.z - __bfloat162float(hz));
    __nv_bfloat16 lw = __float2bfloat16(a.w - __bfloat162float(hw));

    __nv_bfloat162 h01 = __nv_bfloat162(hx, hy), h23 = __nv_bfloat162(hz, hw);
    __nv_bfloat162 l01 = __nv_bfloat162(lx, ly), l23 = __nv_bfloat162(lz, lw);
    uint2 hv, lv;
    hv.x = *reinterpret_cast<uint32_t*>(&h01); hv.y = *reinterpret_cast<uint32_t*>(&h23);
    lv.x = *reinterpret_cast<uint32_t*>(&l01); lv.y = *reinterpret_cast<uint32_t*>(&l23);
    *reinterpret_cast<uint2*>(d0 + (size_t)i * 4) = hv;
    *reinterpret_cast<uint2*>(d1 + (size_t)i * 4) = lv;
}

// ============================================================================
// Kernel 1b: zero the stats accumulators (graph replays need fresh zeros)
// ============================================================================
__global__ void k_zero() {
    int i = blockIdx.x * 256 + threadIdx.x;   // grid 1024 -> 262144 covers NVB*D_OUTF
    g_psum[i] = 0.f;
    g_psum2[i] = 0.f;
}

// ============================================================================
// Kernel 2: GEMM x = A @ W^T, 2-term bf16 split (3 MMA passes), CTA 128x256,
//   512 threads (2m x 8n warps, warp tile 64x32), BK=32, 3-stage cp.async.
//   Epilogue: writes g_x (streaming) + GhostBN partial sums via atomics.
// ============================================================================
#define BK        32
#define ROW_PAD   40                       // bf16 per smem row (80 bytes)
#define TILE_A_B  (128 * ROW_PAD * 2)      // 10240 bytes (128 rows)
#define TILE_W_B  (256 * ROW_PAD * 2)      // 20480 bytes (256 rows)
#define STAGE_B   (2 * TILE_A_B + 2 * TILE_W_B)  // 61440
#define NSTAGE    3
#define GEMM_SMEM (NSTAGE * STAGE_B)       // 184320
#define KTILES    (D_INF / BK)             // 16

__device__ __forceinline__ void gemm_load_stage(
    uint32_t smem_base, int stage, int m0, int n0, int k0, int tid)
{
    const __nv_bfloat16* A0p = g_A0 + (size_t)m0 * D_INF + k0;
    const __nv_bfloat16* A1p = g_A1 + (size_t)m0 * D_INF + k0;
    const __nv_bfloat16* W0p = g_W0 + (size_t)n0 * D_INF + k0;
    const __nv_bfloat16* W1p = g_W1 + (size_t)n0 * D_INF + k0;
    uint32_t sbase = smem_base + stage * STAGE_B;
#pragma unroll
    for (int i = 0; i < 6; i++) {
        int c = tid + 512 * i;               // 0..3071
        const __nv_bfloat16* src;
        uint32_t dst;
        if (c < 1024) {                      // A0 (512 chunks) then A1
            const __nv_bfloat16* b = (c < 512) ? A0p : A1p;
            int idx = c & 511, row = idx >> 2, seg = idx & 3;
            src = b + (size_t)row * D_INF + seg * 8;
            dst = sbase + ((c < 512) ? 0 : TILE_A_B) + row * (ROW_PAD * 2) + seg * 16;
        } else {                             // W0 (1024 chunks) then W1
            int c2 = c - 1024;
            const __nv_bfloat16* b = (c2 < 1024) ? W0p : W1p;
            int idx = c2 & 1023, row = idx >> 2, seg = idx & 3;
            src = b + (size_t)row * D_INF + seg * 8;
            dst = sbase + 2 * TILE_A_B + ((c2 < 1024) ? 0 : TILE_W_B)
                  + row * (ROW_PAD * 2) + seg * 16;
        }
        CP_ASYNC_16(dst, src);
    }
}

__global__ void __launch_bounds__(512, 1) k_gemm() {
    extern __shared__ char smem[];
    const uint32_t smem_base = smem_to_u32(smem);
    const int tid = threadIdx.x;
    const int wid = tid >> 5, lid = tid & 31;
    const int m0 = blockIdx.y * 128;
    const int n0 = blockIdx.x * 256;
    const int wm = wid & 1;                 // m offset 64*wm
    const int wn = wid >> 1;                // 0..7 -> n offset 32*wn

    uint32_t offA[4];
#pragma unroll
    for (int mf = 0; mf < 4; mf++)
        offA[mf] = (uint32_t)((wm * 64 + mf * 16 + (lid & 15)) * (ROW_PAD * 2)
                              + (lid >> 4) * 16);
    uint32_t offB[2];
#pragma unroll
    for (int g = 0; g < 2; g++)
        offB[g] = (uint32_t)((wn * 32 + g * 16 + (lid & 7) + ((lid >> 4) << 3)) * (ROW_PAD * 2)
                             + ((lid >> 3) & 1) * 16);

    float acc[4][4][4];
#pragma unroll
    for (int mf = 0; mf < 4; mf++)
#pragma unroll
        for (int nf = 0; nf < 4; nf++)
#pragma unroll
            for (int r = 0; r < 4; r++) acc[mf][nf][r] = 0.f;

    gemm_load_stage(smem_base, 0, m0, n0, 0, tid);
    CP_ASYNC_COMMIT();
    gemm_load_stage(smem_base, 1, m0, n0, BK, tid);
    CP_ASYNC_COMMIT();

    for (int kt = 0; kt < KTILES; kt++) {
        CP_ASYNC_WAIT_1();
        __syncthreads();

        if (kt + 2 < KTILES)
            gemm_load_stage(smem_base, (kt + 2) % NSTAGE, m0, n0, (kt + 2) * BK, tid);
        CP_ASYNC_COMMIT();

        uint32_t sbase = smem_base + (kt % NSTAGE) * STAGE_B;
        uint32_t sA0 = sbase, sA1 = sbase + TILE_A_B;
        uint32_t sW0 = sbase + 2 * TILE_A_B, sW1 = sW0 + TILE_W_B;

#pragma unroll
        for (int kk = 0; kk < 2; kk++) {
            uint32_t koff = kk * 32;

            uint32_t a0[4][4], a1[4][4];
#pragma unroll
            for (int mf = 0; mf < 4; mf++) {
                LDMATRIX_X4(a0[mf][0], a0[mf][1], a0[mf][2], a0[mf][3], sA0 + offA[mf] + koff);
                LDMATRIX_X4(a1[mf][0], a1[mf][1], a1[mf][2], a1[mf][3], sA1 + offA[mf] + koff);
            }
            uint32_t b0[2][4], b1[2][4];
#pragma unroll
            for (int g = 0; g < 2; g++) {
                LDMATRIX_X4(b0[g][0], b0[g][1], b0[g][2], b0[g][3], sW0 + offB[g] + koff);
                LDMATRIX_X4(b1[g][0], b1[g][1], b1[g][2], b1[g][3], sW1 + offB[g] + koff);
            }
            // Term-major ordering: same-acc dependency distance = 16 MMAs
#pragma unroll
            for (int mf = 0; mf < 4; mf++)
#pragma unroll
                for (int nf = 0; nf < 4; nf++) {
                    int g = nf >> 1, p = (nf & 1) * 2;
                    MMA_16816(acc[mf][nf], a0[mf], b0[g][p], b0[g][p + 1]);
                }
#pragma unroll
            for (int mf = 0; mf < 4; mf++)
#pragma unroll
                for (int nf = 0; nf < 4; nf++) {
                    int g = nf >> 1, p = (nf & 1) * 2;
                    MMA_16816(acc[mf][nf], a0[mf], b1[g][p], b1[g][p + 1]);
                }
#pragma unroll
            for (int mf = 0; mf < 4; mf++)
#pragma unroll
                for (int nf = 0; nf < 4; nf++) {
                    int g = nf >> 1, p = (nf & 1) * 2;
                    MMA_16816(acc[mf][nf], a1[mf], b0[g][p], b0[g][p + 1]);
                }
        }
        __syncthreads();
    }

    // ---- Epilogue: store x (streaming) ----
    const int rbase = m0 + wm * 64 + (lid >> 2);
    const int cbase = n0 + wn * 32 + (lid & 3) * 2;
#pragma unroll
    for (int mf = 0; mf < 4; mf++) {
#pragma unroll
        for (int nf = 0; nf < 4; nf++) {
            int r0 = rbase + mf * 16;
            int c = cbase + nf * 8;
            float2 v0 = make_float2(acc[mf][nf][0], acc[mf][nf][1]);
            float2 v1 = make_float2(acc[mf][nf][2], acc[mf][nf][3]);
            __stcs(reinterpret_cast<float2*>(g_x + (size_t)r0 * D_OUTF + c), v0);
            __stcs(reinterpret_cast<float2*>(g_x + (size_t)(r0 + 8) * D_OUTF + c), v1);
        }
    }

    // ---- Epilogue: GhostBN partial sums (warp covers 64 rows x 32 cols) ----
    float s[8], q[8];
#pragma unroll
    for (int nf = 0; nf < 4; nf++) {
#pragma unroll
        for (int w = 0; w < 2; w++) {
            float ss = 0.f, qq = 0.f;
#pragma unroll
            for (int mf = 0; mf < 4; mf++) {
                float v0 = acc[mf][nf][w], v1 = acc[mf][nf][w + 2];
                ss += v0 + v1;
                qq = fmaf(v0, v0, qq);
                qq = fmaf(v1, v1, qq);
            }
            s[nf * 2 + w] = ss;
            q[nf * 2 + w] = qq;
        }
    }
#pragma unroll
    for (int o = 4; o < 32; o <<= 1) {
#pragma unroll
        for (int t = 0; t < 8; t++) {
            s[t] += __shfl_xor_sync(0xffffffffu, s[t], o);
            q[t] += __shfl_xor_sync(0xffffffffu, q[t], o);
        }
    }
    if ((lid >> 2) == 0) {
        const int vb = m0 >> 8;
        float* ps = g_psum  + (size_t)vb * D_OUTF;
        float* pq = g_psum2 + (size_t)vb * D_OUTF;
#pragma unroll
        for (int nf = 0; nf < 4; nf++) {
#pragma unroll
            for (int w = 0; w < 2; w++) {
                int c = cbase + nf * 8 + w;
                atomicAdd(ps + c, s[nf * 2 + w]);
                atomicAdd(pq + c, q[nf * 2 + w]);
            }
        }
    }
}

// ============================================================================
// Kernel 3: fold partial sums -> scale/shift per (vb, d)
// ============================================================================
__global__ void k_stats2(const float* __restrict__ gamma, const float* __restrict__ beta) {
    int d = blockIdx.x * 256 + threadIdx.x;
    int vb = blockIdx.y;
    size_t i = (size_t)vb * D_OUTF + d;
    float sm = g_psum[i], sq = g_psum2[i];
    float mean = sm * (1.f / VBSZ);
    float var = fmaxf(sq * (1.f / VBSZ) - mean * mean, 0.f);
    float rstd = rsqrtf(var + BN_EPS);
    float sc = rstd * gamma[d];
    g_scale[i] = sc;
    g_shift[i] = beta[d] - mean * sc;
}

// ============================================================================
// Kernel 4: fused BN*prior + sparsemax. TWO warps per row (z[32]/lane),
//   Newton iterations on f(tau)=sum(max(z-tau,0))-1 from tau0=max-1:
//   monotone from below on convex piecewise-linear f -> fixed 16 iters.
// ============================================================================
__global__ void __launch_bounds__(256) k_sparsemax(const float* __restrict__ priors,
                                                   float* __restrict__ out) {
    __shared__ float  s_max[4][2];
    __shared__ float2 s_red[2][4][2];
    const int tid = threadIdx.x;
    const int wid = tid >> 5, lid = tid & 31;
    const int rs = wid >> 1, half = wid & 1;         // 4 rows/block, 2 warps/row
    const int row = blockIdx.x * 4 + rs;
    const int vb = row >> 8;

    const float4* xv = reinterpret_cast<const float4*>(g_x + (size_t)row * D_OUTF) + half * 256;
    const float4* pv = reinterpret_cast<const float4*>(priors + (size_t)row * D_OUTF) + half * 256;
    const float4* sv = reinterpret_cast<const float4*>(g_scale + (size_t)vb * D_OUTF) + half * 256;
    const float4* hv = reinterpret_cast<const float4*>(g_shift + (size_t)vb * D_OUTF) + half * 256;

    float z[32];
#pragma unroll
    for (int j = 0; j < 8; j++) {
        int c = lid + 32 * j;
        float4 x = __ldcs(xv + c);
        float4 p = __ldcs(pv + c);
        float4 sc = sv[c];
        float4 sh = hv[c];
        z[4 * j + 0] = fmaf(x.x, sc.x, sh.x) * p.x;
        z[4 * j + 1] = fmaf(x.y, sc.y, sh.y) * p.y;
        z[4 * j + 2] = fmaf(x.z, sc.z, sh.z) * p.z;
        z[4 * j + 3] = fmaf(x.w, sc.w, sh.w) * p.w;
    }

    // row max across both warps
    float m = z[0];
#pragma unroll
    for (int i = 1; i < 32; i++) m = fmaxf(m, z[i]);
#pragma unroll
    for (int o = 16; o; o >>= 1) m = fmaxf(m, __shfl_xor_sync(0xffffffffu, m, o));
    if (lid == 0) s_max[rs][half] = m;
    __syncthreads();
    m = fmaxf(s_max[rs][0], s_max[rs][1]);

    // Newton: tau_{k+1} = (S(tau_k) - 1) / C(tau_k); start below the root.
    float tau = m - 1.f;
#pragma unroll 1
    for (int it = 0; it < 16; it++) {
        float S = 0.f, C = 0.f;
#pragma unroll
        for (int i = 0; i < 32; i++) {
            if (z[i] > tau) { S += z[i]; C += 1.f; }
        }
#pragma unroll
        for (int o = 16; o; o >>= 1) {
            S += __shfl_xor_sync(0xffffffffu, S, o);
            C += __shfl_xor_sync(0xffffffffu, C, o);
        }
        if (lid == 0) s_red[it & 1][rs][half] = make_float2(S, C);
        __syncthreads();
        float2 a = s_red[it & 1][rs][0], b = s_red[it & 1][rs][1];
        tau = (a.x + b.x - 1.f) / (a.y + b.y);
    }

    float4* ov = reinterpret_cast<float4*>(out + (size_t)row * D_OUTF) + half * 256;
#pragma unroll
    for (int j = 0; j < 8; j++) {
        int c = lid + 32 * j;
        float4 v;
        v.x = fmaxf(z[4 * j + 0] - tau, 0.f);
        v.y = fmaxf(z[4 * j + 1] - tau, 0.f);
        v.z = fmaxf(z[4 * j + 2] - tau, 0.f);
        v.w = fmaxf(z[4 * j + 3] - tau, 0.f);
        __stcs(ov + c, v);
    }
}

// ============================================================================
// Launch
// ============================================================================
extern "C" void kernel_launch(void* const* d_in, const int* in_sizes, int n_in,
                              void* d_out, int out_size) {
    const float* priors = (const float*)d_in[0];   // [32768, 2048]
    const float* feat   = (const float*)d_in[1];   // [32768, 512]
    const float* Wm     = (const float*)d_in[2];   // [2048, 512]
    const float* gamma  = (const float*)d_in[3];   // [2048]
    const float* beta   = (const float*)d_in[4];   // [2048]
    float* out = (float*)d_out;

    static bool attr_set = false;
    if (!attr_set) {
        cudaFuncSetAttribute(k_gemm, cudaFuncAttributeMaxDynamicSharedMemorySize, GEMM_SMEM);
        attr_set = true;
    }

    k_split<<<17408, 256>>>(feat, Wm);
    k_zero<<<(NVB * D_OUTF) / 256, 256>>>();
    k_gemm<<<dim3(8, 256), 512, GEMM_SMEM>>>();
    k_stats2<<<dim3(D_OUTF / 256, NVB), 256>>>(gamma, beta);
    k_sparsemax<<<B_ROWS / 4, 256>>>(priors, out);
}

// round 5
// speedup vs baseline: 1.4366x; 1.4366x over previous
#include <cuda_runtime.h>
#include <cuda_bf16.h>
#include <cstdint>

// ============================================================================
// Problem constants
// ============================================================================
#define B_ROWS 32768
#define D_INF  512
#define D_OUTF 2048
#define VBSZ   256
#define NVB    (B_ROWS / VBSZ)   // 128
#define BN_EPS 1e-5f

// ============================================================================
// Device scratch (static globals; no cudaMalloc allowed)
// ============================================================================
__device__ __nv_bfloat16 g_A0[(size_t)B_ROWS * D_INF];   // hi bf16 of feat
__device__ __nv_bfloat16 g_A1[(size_t)B_ROWS * D_INF];   // lo bf16 of feat
__device__ __nv_bfloat16 g_W0[(size_t)D_OUTF * D_INF];   // hi bf16 of W
__device__ __nv_bfloat16 g_W1[(size_t)D_OUTF * D_INF];   // lo bf16 of W
__device__ float         g_x [(size_t)B_ROWS * D_OUTF];  // GEMM result
__device__ float         g_psum [(size_t)NVB * D_OUTF];  // col sums per vb
__device__ float         g_psum2[(size_t)NVB * D_OUTF];  // col sumsq per vb
__device__ float         g_scale[(size_t)NVB * D_OUTF];  // rstd*gamma
__device__ float         g_shift[(size_t)NVB * D_OUTF];  // beta - mean*rstd*gamma

// ============================================================================
// PTX helpers (base ISA only: cp.async + ldmatrix + mma.sync)
// ============================================================================
__device__ __forceinline__ uint32_t smem_to_u32(const void* p) {
    uint32_t a;
    asm("{ .reg .u64 t; cvta.to.shared.u64 t, %1; cvt.u32.u64 %0, t; }" : "=r"(a) : "l"(p));
    return a;
}

#define CP_ASYNC_16(dst_u32, src_ptr) \
    asm volatile("cp.async.cg.shared.global [%0], [%1], 16;" :: "r"(dst_u32), "l"(src_ptr))
#define CP_ASYNC_COMMIT() asm volatile("cp.async.commit_group;" ::: "memory")
#define CP_ASYNC_WAIT_1() asm volatile("cp.async.wait_group 1;" ::: "memory")

#define LDMATRIX_X4(r0, r1, r2, r3, addr) \
    asm volatile("ldmatrix.sync.aligned.m8n8.x4.shared.b16 {%0,%1,%2,%3}, [%4];" \
                 : "=r"(r0), "=r"(r1), "=r"(r2), "=r"(r3) : "r"(addr))

#define MMA_16816(d, a, b0, b1) \
    asm volatile("mma.sync.aligned.m16n8k16.row.col.f32.bf16.bf16.f32 " \
                 "{%0,%1,%2,%3}, {%4,%5,%6,%7}, {%8,%9}, {%0,%1,%2,%3};" \
                 : "+f"((d)[0]), "+f"((d)[1]), "+f"((d)[2]), "+f"((d)[3]) \
                 : "r"((a)[0]), "r"((a)[1]), "r"((a)[2]), "r"((a)[3]), "r"(b0), "r"(b1))

// ============================================================================
// Kernel 1: split fp32 -> (bf16 hi, bf16 lo) for A (feat) and W
// ============================================================================
__global__ void k_split(const float* __restrict__ feat, const float* __restrict__ Wm) {
    constexpr int NA4 = B_ROWS * D_INF / 4;   // 4194304
    constexpr int NW4 = D_OUTF * D_INF / 4;   // 262144
    int idx = blockIdx.x * blockDim.x + threadIdx.x;
    const float* src;
    __nv_bfloat16 *d0, *d1;
    int i;
    if (idx < NA4) { src = feat; d0 = g_A0; d1 = g_A1; i = idx; }
    else if (idx < NA4 + NW4) { src = Wm; d0 = g_W0; d1 = g_W1; i = idx - NA4; }
    else return;

    float4 a = reinterpret_cast<const float4*>(src)[i];
    __nv_bfloat16 hx = __float2bfloat16(a.x), hy = __float2bfloat16(a.y);
    __nv_bfloat16 hz = __float2bfloat16(a.z), hw = __float2bfloat16(a.w);
    __nv_bfloat16 lx = __float2bfloat16(a.x - __bfloat162float(hx));
    __nv_bfloat16 ly = __float2bfloat16(a.y - __bfloat162float(hy));
    __nv_bfloat16 lz = __float2bfloat16(a.z - __bfloat162float(hz));
    __nv_bfloat16 lw = __float2bfloat16(a.w - __bfloat162float(hw));

    __nv_bfloat162 h01 = __nv_bfloat162(hx, hy), h23 = __nv_bfloat162(hz, hw);
    __nv_bfloat162 l01 = __nv_bfloat162(lx, ly), l23 = __nv_bfloat162(lz, lw);
    uint2 hv, lv;
    hv.x = *reinterpret_cast<uint32_t*>(&h01); hv.y = *reinterpret_cast<uint32_t*>(&h23);
    lv.x = *reinterpret_cast<uint32_t*>(&l01); lv.y = *reinterpret_cast<uint32_t*>(&l23);
    *reinterpret_cast<uint2*>(d0 + (size_t)i * 4) = hv;
    *reinterpret_cast<uint2*>(d1 + (size_t)i * 4) = lv;
}

// ============================================================================
// Kernel 1b: zero the stats accumulators (graph replays need fresh zeros)
// ============================================================================
__global__ void k_zero() {
    int i = blockIdx.x * 256 + threadIdx.x;
    g_psum[i] = 0.f;
    g_psum2[i] = 0.f;
}

// ============================================================================
// Kernel 2: GEMM x = A @ W^T (R2-exact config: CTA 128x128, 256 thr, BK=32,
//   3-stage cp.async, 8 warps 2m x 4n, warp tile 64x32, ROW_PAD=40).
//   Epilogue additionally accumulates GhostBN partial sums via atomics.
// ============================================================================
#define BK        32
#define ROW_PAD   40                       // bf16 per smem row (80 bytes)
#define TILE_B    (128 * ROW_PAD * 2)      // 10240 bytes per 128x32 tile
#define STAGE_B   (4 * TILE_B)             // A0,A1,W0,W1 = 40960 bytes
#define NSTAGE    3
#define GEMM_SMEM (NSTAGE * STAGE_B)       // 122880 bytes
#define KTILES    (D_INF / BK)             // 16

__device__ __forceinline__ void gemm_load_stage(
    uint32_t smem_base, int stage, int m0, int n0, int k0, int tid)
{
    const __nv_bfloat16* bases[4] = {
        g_A0 + (size_t)m0 * D_INF + k0,
        g_A1 + (size_t)m0 * D_INF + k0,
        g_W0 + (size_t)n0 * D_INF + k0,
        g_W1 + (size_t)n0 * D_INF + k0
    };
    uint32_t sbase = smem_base + stage * STAGE_B;
#pragma unroll
    for (int i = 0; i < 8; i++) {
        int chunk = tid + 256 * i;          // 0..2047
        int tile = chunk >> 9;              // 0..3
        int idx = chunk & 511;
        int row = idx >> 2;
        int seg = idx & 3;
        const __nv_bfloat16* src = bases[tile] + (size_t)row * D_INF + seg * 8;
        uint32_t dst = sbase + tile * TILE_B + row * (ROW_PAD * 2) + seg * 16;
        CP_ASYNC_16(dst, src);
    }
}

__global__ void __launch_bounds__(256, 1) k_gemm() {
    extern __shared__ char smem[];
    const uint32_t smem_base = smem_to_u32(smem);
    const int tid = threadIdx.x;
    const int wid = tid >> 5, lid = tid & 31;
    const int m0 = blockIdx.y * 128;
    const int n0 = blockIdx.x * 128;
    const int wm = wid & 1;                 // 0..1 -> m offset 64*wm
    const int wn = wid >> 1;                // 0..3 -> n offset 32*wn

    uint32_t offA[4];
#pragma unroll
    for (int mf = 0; mf < 4; mf++)
        offA[mf] = (uint32_t)((wm * 64 + mf * 16 + (lid & 15)) * (ROW_PAD * 2)
                              + (lid >> 4) * 16);
    uint32_t offB[2];
#pragma unroll
    for (int g = 0; g < 2; g++)
        offB[g] = (uint32_t)((wn * 32 + g * 16 + (lid & 7) + ((lid >> 4) << 3)) * (ROW_PAD * 2)
                             + ((lid >> 3) & 1) * 16);

    float acc[4][4][4];
#pragma unroll
    for (int mf = 0; mf < 4; mf++)
#pragma unroll
        for (int nf = 0; nf < 4; nf++)
#pragma unroll
            for (int r = 0; r < 4; r++) acc[mf][nf][r] = 0.f;

    gemm_load_stage(smem_base, 0, m0, n0, 0, tid);
    CP_ASYNC_COMMIT();
    gemm_load_stage(smem_base, 1, m0, n0, BK, tid);
    CP_ASYNC_COMMIT();

    for (int kt = 0; kt < KTILES; kt++) {
        CP_ASYNC_WAIT_1();
        __syncthreads();

        if (kt + 2 < KTILES)
            gemm_load_stage(smem_base, (kt + 2) % NSTAGE, m0, n0, (kt + 2) * BK, tid);
        CP_ASYNC_COMMIT();

        uint32_t sbase = smem_base + (kt % NSTAGE) * STAGE_B;
        uint32_t sA0 = sbase, sA1 = sbase + TILE_B;
        uint32_t sW0 = sbase + 2 * TILE_B, sW1 = sbase + 3 * TILE_B;

#pragma unroll
        for (int kk = 0; kk < 2; kk++) {
            uint32_t koff = kk * 32;

            uint32_t a0[4][4], a1[4][4];
#pragma unroll
            for (int mf = 0; mf < 4; mf++) {
                LDMATRIX_X4(a0[mf][0], a0[mf][1], a0[mf][2], a0[mf][3], sA0 + offA[mf] + koff);
                LDMATRIX_X4(a1[mf][0], a1[mf][1], a1[mf][2], a1[mf][3], sA1 + offA[mf] + koff);
            }
            uint32_t b0[2][4], b1[2][4];
#pragma unroll
            for (int g = 0; g < 2; g++) {
                LDMATRIX_X4(b0[g][0], b0[g][1], b0[g][2], b0[g][3], sW0 + offB[g] + koff);
                LDMATRIX_X4(b1[g][0], b1[g][1], b1[g][2], b1[g][3], sW1 + offB[g] + koff);
            }
#pragma unroll
            for (int mf = 0; mf < 4; mf++) {
#pragma unroll
                for (int nf = 0; nf < 4; nf++) {
                    int g = nf >> 1, p = (nf & 1) * 2;
                    MMA_16816(acc[mf][nf], a0[mf], b0[g][p], b0[g][p + 1]);
                    MMA_16816(acc[mf][nf], a0[mf], b1[g][p], b1[g][p + 1]);
                    MMA_16816(acc[mf][nf], a1[mf], b0[g][p], b0[g][p + 1]);
                }
            }
        }
        __syncthreads();
    }

    // ---- Epilogue: store x (streaming) ----
    const int rbase = m0 + wm * 64 + (lid >> 2);
    const int cbase = n0 + wn * 32 + (lid & 3) * 2;
#pragma unroll
    for (int mf = 0; mf < 4; mf++) {
#pragma unroll
        for (int nf = 0; nf < 4; nf++) {
            int r0 = rbase + mf * 16;
            int c = cbase + nf * 8;
            float2 v0 = make_float2(acc[mf][nf][0], acc[mf][nf][1]);
            float2 v1 = make_float2(acc[mf][nf][2], acc[mf][nf][3]);
            __stcs(reinterpret_cast<float2*>(g_x + (size_t)r0 * D_OUTF + c), v0);
            __stcs(reinterpret_cast<float2*>(g_x + (size_t)(r0 + 8) * D_OUTF + c), v1);
        }
    }

    // ---- Epilogue: GhostBN partial sums. Warp covers 64 rows x 32 cols;
    //      all 128 CTA rows belong to one virtual batch half -> vb = m0>>8.
    float s[8], q[8];
#pragma unroll
    for (int nf = 0; nf < 4; nf++) {
#pragma unroll
        for (int w = 0; w < 2; w++) {
            float ss = 0.f, qq = 0.f;
#pragma unroll
            for (int mf = 0; mf < 4; mf++) {
                float v0 = acc[mf][nf][w], v1 = acc[mf][nf][w + 2];
                ss += v0 + v1;
                qq = fmaf(v0, v0, qq);
                qq = fmaf(v1, v1, qq);
            }
            s[nf * 2 + w] = ss;
            q[nf * 2 + w] = qq;
        }
    }
    // reduce over the 8 lane-groups sharing each column (lanes differing in bits 2..4)
#pragma unroll
    for (int o = 4; o < 32; o <<= 1) {
#pragma unroll
        for (int t = 0; t < 8; t++) {
            s[t] += __shfl_xor_sync(0xffffffffu, s[t], o);
            q[t] += __shfl_xor_sync(0xffffffffu, q[t], o);
        }
    }
    if ((lid >> 2) == 0) {
        const int vb = m0 >> 8;
        float* ps = g_psum  + (size_t)vb * D_OUTF;
        float* pq = g_psum2 + (size_t)vb * D_OUTF;
#pragma unroll
        for (int nf = 0; nf < 4; nf++) {
#pragma unroll
            for (int w = 0; w < 2; w++) {
                int c = cbase + nf * 8 + w;
                atomicAdd(ps + c, s[nf * 2 + w]);
                atomicAdd(pq + c, q[nf * 2 + w]);
            }
        }
    }
}

// ============================================================================
// Kernel 3: fold partial sums -> scale/shift per (vb, d)
// ============================================================================
__global__ void k_stats2(const float* __restrict__ gamma, const float* __restrict__ beta) {
    int d = blockIdx.x * 256 + threadIdx.x;
    int vb = blockIdx.y;
    size_t i = (size_t)vb * D_OUTF + d;
    float sm = g_psum[i], sq = g_psum2[i];
    float mean = sm * (1.f / VBSZ);
    float var = fmaxf(sq * (1.f / VBSZ) - mean * mean, 0.f);
    float rstd = rsqrtf(var + BN_EPS);
    float sc = rstd * gamma[d];
    g_scale[i] = sc;
    g_shift[i] = beta[d] - mean * sc;
}

// ============================================================================
// Kernel 4: fused BN*prior + sparsemax. ONE 128-thread block per row,
//   z[16]/lane (no spills). Newton on f(tau)=sum(max(z-tau,0))-1 from
//   tau0 = max-1 (monotone from below, support strictly shrinks) x12 iters.
//   One syncthreads per iteration (double-buffered smem reduction).
// ============================================================================
__global__ void __launch_bounds__(128) k_sparsemax(const float* __restrict__ priors,
                                                   float* __restrict__ out) {
    __shared__ float  s_max[4];
    __shared__ float2 s_red[2][4];
    const int tid = threadIdx.x;
    const int wid = tid >> 5, lid = tid & 31;
    const int row = blockIdx.x;
    const int vb = row >> 8;

    const float4* xv = reinterpret_cast<const float4*>(g_x + (size_t)row * D_OUTF);
    const float4* pv = reinterpret_cast<const float4*>(priors + (size_t)row * D_OUTF);
    const float4* sv = reinterpret_cast<const float4*>(g_scale + (size_t)vb * D_OUTF);
    const float4* hv = reinterpret_cast<const float4*>(g_shift + (size_t)vb * D_OUTF);

    float z[16];
#pragma unroll
    for (int j = 0; j < 4; j++) {
        int c = tid + 128 * j;               // float4 index 0..511, coalesced
        float4 x = __ldcs(xv + c);
        float4 p = __ldcs(pv + c);
        float4 sc = sv[c];
        float4 sh = hv[c];
        z[4 * j + 0] = fmaf(x.x, sc.x, sh.x) * p.x;
        z[4 * j + 1] = fmaf(x.y, sc.y, sh.y) * p.y;
        z[4 * j + 2] = fmaf(x.z, sc.z, sh.z) * p.z;
        z[4 * j + 3] = fmaf(x.w, sc.w, sh.w) * p.w;
    }

    // block max
    float m = z[0];
#pragma unroll
    for (int i = 1; i < 16; i++) m = fmaxf(m, z[i]);
#pragma unroll
    for (int o = 16; o; o >>= 1) m = fmaxf(m, __shfl_xor_sync(0xffffffffu, m, o));
    if (lid == 0) s_max[wid] = m;
    __syncthreads();
    m = fmaxf(fmaxf(s_max[0], s_max[1]), fmaxf(s_max[2], s_max[3]));

    // Newton: tau_{k+1} = (S(tau_k) - 1) / C(tau_k)
    float tau = m - 1.f;
#pragma unroll 1
    for (int it = 0; it < 12; it++) {
        float S = 0.f, C = 0.f;
#pragma unroll
        for (int i = 0; i < 16; i++) {
            if (z[i] > tau) { S += z[i]; C += 1.f; }
        }
#pragma unroll
        for (int o = 16; o; o >>= 1) {
            S += __shfl_xor_sync(0xffffffffu, S, o);
            C += __shfl_xor_sync(0xffffffffu, C, o);
        }
        if (lid == 0) s_red[it & 1][wid] = make_float2(S, C);
        __syncthreads();
        float2 r0 = s_red[it & 1][0], r1 = s_red[it & 1][1];
        float2 r2 = s_red[it & 1][2], r3 = s_red[it & 1][3];
        tau = (r0.x + r1.x + r2.x + r3.x - 1.f) / (r0.y + r1.y + r2.y + r3.y);
    }

    float4* ov = reinterpret_cast<float4*>(out + (size_t)row * D_OUTF);
#pragma unroll
    for (int j = 0; j < 4; j++) {
        int c = tid + 128 * j;
        float4 v;
        v.x = fmaxf(z[4 * j + 0] - tau, 0.f);
        v.y = fmaxf(z[4 * j + 1] - tau, 0.f);
        v.z = fmaxf(z[4 * j + 2] - tau, 0.f);
        v.w = fmaxf(z[4 * j + 3] - tau, 0.f);
        __stcs(ov + c, v);
    }
}

// ============================================================================
// Launch
// ============================================================================
extern "C" void kernel_launch(void* const* d_in, const int* in_sizes, int n_in,
                              void* d_out, int out_size) {
    const float* priors = (const float*)d_in[0];   // [32768, 2048]
    const float* feat   = (const float*)d_in[1];   // [32768, 512]
    const float* Wm     = (const float*)d_in[2];   // [2048, 512]
    const float* gamma  = (const float*)d_in[3];   // [2048]
    const float* beta   = (const float*)d_in[4];   // [2048]
    float* out = (float*)d_out;

    cudaFuncSetAttribute(k_gemm, cudaFuncAttributeMaxDynamicSharedMemorySize, GEMM_SMEM);

    k_split<<<17408, 256>>>(feat, Wm);
    k_zero<<<(NVB * D_OUTF) / 256, 256>>>();
    k_gemm<<<dim3(16, 256), 256, GEMM_SMEM>>>();
    k_stats2<<<dim3(D_OUTF / 256, NVB), 256>>>(gamma, beta);
    k_sparsemax<<<B_ROWS, 128>>>(priors, out);
}

// round 7
// speedup vs baseline: 1.8330x; 1.2759x over previous
#include <cuda_runtime.h>
#include <cuda_bf16.h>
#include <cuda_fp16.h>
#include <cstdint>

// ============================================================================
// Problem constants
// ============================================================================
#define B_ROWS 32768
#define D_INF  512
#define D_OUTF 2048
#define VBSZ   256
#define NVB    (B_ROWS / VBSZ)   // 128
#define BN_EPS 1e-5f

// ============================================================================
// Device scratch (static globals; no cudaMalloc allowed)
// ============================================================================
__device__ __half g_A0[(size_t)B_ROWS * D_INF];   // hi fp16 of feat
__device__ __half g_A1[(size_t)B_ROWS * D_INF];   // lo fp16 of feat
__device__ __half g_W0[(size_t)D_OUTF * D_INF];   // fp16 of W
__device__ float  g_x [(size_t)B_ROWS * D_OUTF];  // GEMM result
__device__ float  g_psum [(size_t)NVB * D_OUTF];  // col sums per vb
__device__ float  g_psum2[(size_t)NVB * D_OUTF];  // col sumsq per vb
__device__ float  g_scale[(size_t)NVB * D_OUTF];  // rstd*gamma
__device__ float  g_shift[(size_t)NVB * D_OUTF];  // beta - mean*rstd*gamma

// ============================================================================
// PTX helpers (base ISA only: cp.async + ldmatrix + mma.sync)
// ============================================================================
__device__ __forceinline__ uint32_t smem_to_u32(const void* p) {
    uint32_t a;
    asm("{ .reg .u64 t; cvta.to.shared.u64 t, %1; cvt.u32.u64 %0, t; }" : "=r"(a) : "l"(p));
    return a;
}

#define CP_ASYNC_16(dst_u32, src_ptr) \
    asm volatile("cp.async.cg.shared.global [%0], [%1], 16;" :: "r"(dst_u32), "l"(src_ptr))
#define CP_ASYNC_COMMIT() asm volatile("cp.async.commit_group;" ::: "memory")
#define CP_ASYNC_WAIT_2() asm volatile("cp.async.wait_group 2;" ::: "memory")

#define LDMATRIX_X4(r0, r1, r2, r3, addr) \
    asm volatile("ldmatrix.sync.aligned.m8n8.x4.shared.b16 {%0,%1,%2,%3}, [%4];" \
                 : "=r"(r0), "=r"(r1), "=r"(r2), "=r"(r3) : "r"(addr))

#define MMA_16816(d, a, b0, b1) \
    asm volatile("mma.sync.aligned.m16n8k16.row.col.f32.f16.f16.f32 " \
                 "{%0,%1,%2,%3}, {%4,%5,%6,%7}, {%8,%9}, {%0,%1,%2,%3};" \
                 : "+f"((d)[0]), "+f"((d)[1]), "+f"((d)[2]), "+f"((d)[3]) \
                 : "r"((a)[0]), "r"((a)[1]), "r"((a)[2]), "r"((a)[3]), "r"(b0), "r"(b1))

// ============================================================================
// Kernel 1: split fp32 A -> (fp16 hi, fp16 lo); round W -> fp16
// ============================================================================
__global__ void k_split(const float* __restrict__ feat, const float* __restrict__ Wm) {
    constexpr int NA4 = B_ROWS * D_INF / 4;   // 4194304
    constexpr int NW4 = D_OUTF * D_INF / 4;   // 262144
    int idx = blockIdx.x * blockDim.x + threadIdx.x;
    if (idx < NA4) {
        float4 a = reinterpret_cast<const float4*>(feat)[idx];
        __half hx = __float2half_rn(a.x), hy = __float2half_rn(a.y);
        __half hz = __float2half_rn(a.z), hw = __float2half_rn(a.w);
        __half lx = __float2half_rn(a.x - __half2float(hx));
        __half ly = __float2half_rn(a.y - __half2float(hy));
        __half lz = __float2half_rn(a.z - __half2float(hz));
        __half lw = __float2half_rn(a.w - __half2float(hw));
        __half2 h01 = __halves2half2(hx, hy), h23 = __halves2half2(hz, hw);
        __half2 l01 = __halves2half2(lx, ly), l23 = __halves2half2(lz, lw);
        uint2 hv, lv;
        hv.x = *reinterpret_cast<uint32_t*>(&h01); hv.y = *reinterpret_cast<uint32_t*>(&h23);
        lv.x = *reinterpret_cast<uint32_t*>(&l01); lv.y = *reinterpret_cast<uint32_t*>(&l23);
        *reinterpret_cast<uint2*>(g_A0 + (size_t)idx * 4) = hv;
        *reinterpret_cast<uint2*>(g_A1 + (size_t)idx * 4) = lv;
    } else if (idx < NA4 + NW4) {
        int i = idx - NA4;
        float4 a = reinterpret_cast<const float4*>(Wm)[i];
        __half2 h01 = __floats2half2_rn(a.x, a.y);
        __half2 h23 = __floats2half2_rn(a.z, a.w);
        uint2 hv;
        hv.x = *reinterpret_cast<uint32_t*>(&h01); hv.y = *reinterpret_cast<uint32_t*>(&h23);
        *reinterpret_cast<uint2*>(g_W0 + (size_t)i * 4) = hv;
    }
}

// ============================================================================
// Kernel 1b: zero the stats accumulators (graph replays need fresh zeros)
// ============================================================================
__global__ void k_zero() {
    int i = blockIdx.x * 256 + threadIdx.x;
    g_psum[i] = 0.f;
    g_psum2[i] = 0.f;
}

// ============================================================================
// Kernel 2: GEMM x = A @ W^T, fp16 2-term split (2 MMAs/k-step).
//   CTA 128x128, 256 thr, BK=32, 4-stage cp.async, warps 2m x 4n (64x32).
//   Epilogue: streaming store of x + GhostBN partial sums via atomics.
// ============================================================================
#define BK        32
#define ROW_PAD   40                       // fp16 per smem row (80 bytes)
#define TILE_B    (128 * ROW_PAD * 2)      // 10240 bytes per 128x32 tile
#define STAGE_B   (3 * TILE_B)             // A0,A1,W0 = 30720 bytes
#define NSTAGE    4
#define GEMM_SMEM (NSTAGE * STAGE_B)       // 122880 bytes
#define KTILES    (D_INF / BK)             // 16

__device__ __forceinline__ void gemm_load_stage(
    uint32_t smem_base, int stage, int m0, int n0, int k0, int tid)
{
    const __half* bases[3] = {
        g_A0 + (size_t)m0 * D_INF + k0,
        g_A1 + (size_t)m0 * D_INF + k0,
        g_W0 + (size_t)n0 * D_INF + k0
    };
    uint32_t sbase = smem_base + stage * STAGE_B;
#pragma unroll
    for (int i = 0; i < 6; i++) {
        int chunk = tid + 256 * i;          // 0..1535
        int tile = chunk >> 9;              // 0..2
        int idx = chunk & 511;
        int row = idx >> 2;
        int seg = idx & 3;
        const __half* src = bases[tile] + (size_t)row * D_INF + seg * 8;
        uint32_t dst = sbase + tile * TILE_B + row * (ROW_PAD * 2) + seg * 16;
        CP_ASYNC_16(dst, src);
    }
}

__global__ void __launch_bounds__(256, 1) k_gemm() {
    extern __shared__ char smem[];
    const uint32_t smem_base = smem_to_u32(smem);
    const int tid = threadIdx.x;
    const int wid = tid >> 5, lid = tid & 31;
    const int m0 = blockIdx.y * 128;
    const int n0 = blockIdx.x * 128;
    const int wm = wid & 1;                 // 0..1 -> m offset 64*wm
    const int wn = wid >> 1;                // 0..3 -> n offset 32*wn

    uint32_t offA[4];
#pragma unroll
    for (int mf = 0; mf < 4; mf++)
        offA[mf] = (uint32_t)((wm * 64 + mf * 16 + (lid & 15)) * (ROW_PAD * 2)
                              + (lid >> 4) * 16);
    uint32_t offB[2];
#pragma unroll
    for (int g = 0; g < 2; g++)
        offB[g] = (uint32_t)((wn * 32 + g * 16 + (lid & 7) + ((lid >> 4) << 3)) * (ROW_PAD * 2)
                             + ((lid >> 3) & 1) * 16);

    float acc[4][4][4];
#pragma unroll
    for (int mf = 0; mf < 4; mf++)
#pragma unroll
        for (int nf = 0; nf < 4; nf++)
#pragma unroll
            for (int r = 0; r < 4; r++) acc[mf][nf][r] = 0.f;

    gemm_load_stage(smem_base, 0, m0, n0, 0, tid);
    CP_ASYNC_COMMIT();
    gemm_load_stage(smem_base, 1, m0, n0, BK, tid);
    CP_ASYNC_COMMIT();
    gemm_load_stage(smem_base, 2, m0, n0, 2 * BK, tid);
    CP_ASYNC_COMMIT();

    for (int kt = 0; kt < KTILES; kt++) {
        CP_ASYNC_WAIT_2();                  // stage kt ready
        __syncthreads();

        if (kt + 3 < KTILES)
            gemm_load_stage(smem_base, (kt + 3) % NSTAGE, m0, n0, (kt + 3) * BK, tid);
        CP_ASYNC_COMMIT();

        uint32_t sbase = smem_base + (kt % NSTAGE) * STAGE_B;
        uint32_t sA0 = sbase, sA1 = sbase + TILE_B;
        uint32_t sW0 = sbase + 2 * TILE_B;

#pragma unroll
        for (int kk = 0; kk < 2; kk++) {
            uint32_t koff = kk * 32;

            uint32_t a0[4][4], a1[4][4];
#pragma unroll
            for (int mf = 0; mf < 4; mf++) {
                LDMATRIX_X4(a0[mf][0], a0[mf][1], a0[mf][2], a0[mf][3], sA0 + offA[mf] + koff);
                LDMATRIX_X4(a1[mf][0], a1[mf][1], a1[mf][2], a1[mf][3], sA1 + offA[mf] + koff);
            }
            uint32_t b0[2][4];
#pragma unroll
            for (int g = 0; g < 2; g++)
                LDMATRIX_X4(b0[g][0], b0[g][1], b0[g][2], b0[g][3], sW0 + offB[g] + koff);

            // Term-major: 16 independent MMAs between same-acc reuse
#pragma unroll
            for (int mf = 0; mf < 4; mf++)
#pragma unroll
                for (int nf = 0; nf < 4; nf++) {
                    int g = nf >> 1, p = (nf & 1) * 2;
                    MMA_16816(acc[mf][nf], a0[mf], b0[g][p], b0[g][p + 1]);
                }
#pragma unroll
            for (int mf = 0; mf < 4; mf++)
#pragma unroll
                for (int nf = 0; nf < 4; nf++) {
                    int g = nf >> 1, p = (nf & 1) * 2;
                    MMA_16816(acc[mf][nf], a1[mf], b0[g][p], b0[g][p + 1]);
                }
        }
        __syncthreads();
    }

    // ---- Epilogue: store x (streaming) ----
    const int rbase = m0 + wm * 64 + (lid >> 2);
    const int cbase = n0 + wn * 32 + (lid & 3) * 2;
#pragma unroll
    for (int mf = 0; mf < 4; mf++) {
#pragma unroll
        for (int nf = 0; nf < 4; nf++) {
            int r0 = rbase + mf * 16;
            int c = cbase + nf * 8;
            float2 v0 = make_float2(acc[mf][nf][0], acc[mf][nf][1]);
            float2 v1 = make_float2(acc[mf][nf][2], acc[mf][nf][3]);
            __stcs(reinterpret_cast<float2*>(g_x + (size_t)r0 * D_OUTF + c), v0);
            __stcs(reinterpret_cast<float2*>(g_x + (size_t)(r0 + 8) * D_OUTF + c), v1);
        }
    }

    // ---- Epilogue: GhostBN partial sums (warp: 64 rows x 32 cols; vb = m0>>8)
    float s[8], q[8];
#pragma unroll
    for (int nf = 0; nf < 4; nf++) {
#pragma unroll
        for (int w = 0; w < 2; w++) {
            float ss = 0.f, qq = 0.f;
#pragma unroll
            for (int mf = 0; mf < 4; mf++) {
                float v0 = acc[mf][nf][w], v1 = acc[mf][nf][w + 2];
                ss += v0 + v1;
                qq = fmaf(v0, v0, qq);
                qq = fmaf(v1, v1, qq);
            }
            s[nf * 2 + w] = ss;
            q[nf * 2 + w] = qq;
        }
    }
#pragma unroll
    for (int o = 4; o < 32; o <<= 1) {
#pragma unroll
        for (int t = 0; t < 8; t++) {
            s[t] += __shfl_xor_sync(0xffffffffu, s[t], o);
            q[t] += __shfl_xor_sync(0xffffffffu, q[t], o);
        }
    }
    if ((lid >> 2) == 0) {
        const int vb = m0 >> 8;
        float* ps = g_psum  + (size_t)vb * D_OUTF;
        float* pq = g_psum2 + (size_t)vb * D_OUTF;
#pragma unroll
        for (int nf = 0; nf < 4; nf++) {
#pragma unroll
            for (int w = 0; w < 2; w++) {
                int c = cbase + nf * 8 + w;
                atomicAdd(ps + c, s[nf * 2 + w]);
                atomicAdd(pq + c, q[nf * 2 + w]);
            }
        }
    }
}

// ============================================================================
// Kernel 3: fold partial sums -> scale/shift per (vb, d)
// ============================================================================
__global__ void k_stats2(const float* __restrict__ gamma, const float* __restrict__ beta) {
    int d = blockIdx.x * 256 + threadIdx.x;
    int vb = blockIdx.y;
    size_t i = (size_t)vb * D_OUTF + d;
    float sm = g_psum[i], sq = g_psum2[i];
    float mean = sm * (1.f / VBSZ);
    float var = fmaxf(sq * (1.f / VBSZ) - mean * mean, 0.f);
    float rstd = rsqrtf(var + BN_EPS);
    float sc = rstd * gamma[d];
    g_scale[i] = sc;
    g_shift[i] = beta[d] - mean * sc;
}

// ============================================================================
// Kernel 4: fused BN*prior + sparsemax. ONE 128-thread block per row,
//   z[16]/lane. Newton on f(tau)=sum(max(z-tau,0))-1 from tau0=max-1, x12.
// ============================================================================
__global__ void __launch_bounds__(128) k_sparsemax(const float* __restrict__ priors,
                                                   float* __restrict__ out) {
    __shared__ float  s_max[4];
    __shared__ float2 s_red[2][4];
    const int tid = threadIdx.x;
    const int wid = tid >> 5, lid = tid & 31;
    const int row = blockIdx.x;
    const int vb = row >> 8;

    const float4* xv = reinterpret_cast<const float4*>(g_x + (size_t)row * D_OUTF);
    const float4* pv = reinterpret_cast<const float4*>(priors + (size_t)row * D_OUTF);
    const float4* sv = reinterpret_cast<const float4*>(g_scale + (size_t)vb * D_OUTF);
    const float4* hv = reinterpret_cast<const float4*>(g_shift + (size_t)vb * D_OUTF);

    float z[16];
#pragma unroll
    for (int j = 0; j < 4; j++) {
        int c = tid + 128 * j;
        float4 x = __ldcs(xv + c);
        float4 p = __ldcs(pv + c);
        float4 sc = sv[c];
        float4 sh = hv[c];
        z[4 * j + 0] = fmaf(x.x, sc.x, sh.x) * p.x;
        z[4 * j + 1] = fmaf(x.y, sc.y, sh.y) * p.y;
        z[4 * j + 2] = fmaf(x.z, sc.z, sh.z) * p.z;
        z[4 * j + 3] = fmaf(x.w, sc.w, sh.w) * p.w;
    }

    float m = z[0];
#pragma unroll
    for (int i = 1; i < 16; i++) m = fmaxf(m, z[i]);
#pragma unroll
    for (int o = 16; o; o >>= 1) m = fmaxf(m, __shfl_xor_sync(0xffffffffu, m, o));
    if (lid == 0) s_max[wid] = m;
    __syncthreads();
    m = fmaxf(fmaxf(s_max[0], s_max[1]), fmaxf(s_max[2], s_max[3]));

    float tau = m - 1.f;
#pragma unroll 1
    for (int it = 0; it < 12; it++) {
        float S = 0.f, C = 0.f;
#pragma unroll
        for (int i = 0; i < 16; i++) {
            if (z[i] > tau) { S += z[i]; C += 1.f; }
        }
#pragma unroll
        for (int o = 16; o; o >>= 1) {
            S += __shfl_xor_sync(0xffffffffu, S, o);
            C += __shfl_xor_sync(0xffffffffu, C, o);
        }
        if (lid == 0) s_red[it & 1][wid] = make_float2(S, C);
        __syncthreads();
        float2 r0 = s_red[it & 1][0], r1 = s_red[it & 1][1];
        float2 r2 = s_red[it & 1][2], r3 = s_red[it & 1][3];
        tau = (r0.x + r1.x + r2.x + r3.x - 1.f) / (r0.y + r1.y + r2.y + r3.y);
    }

    float4* ov = reinterpret_cast<float4*>(out + (size_t)row * D_OUTF);
#pragma unroll
    for (int j = 0; j < 4; j++) {
        int c = tid + 128 * j;
        float4 v;
        v.x = fmaxf(z[4 * j + 0] - tau, 0.f);
        v.y = fmaxf(z[4 * j + 1] - tau, 0.f);
        v.z = fmaxf(z[4 * j + 2] - tau, 0.f);
        v.w = fmaxf(z[4 * j + 3] - tau, 0.f);
        __stcs(ov + c, v);
    }
}

// ============================================================================
// Launch
// ============================================================================
extern "C" void kernel_launch(void* const* d_in, const int* in_sizes, int n_in,
                              void* d_out, int out_size) {
    const float* priors = (const float*)d_in[0];   // [32768, 2048]
    const float* feat   = (const float*)d_in[1];   // [32768, 512]
    const float* Wm     = (const float*)d_in[2];   // [2048, 512]
    const float* gamma  = (const float*)d_in[3];   // [2048]
    const float* beta   = (const float*)d_in[4];   // [2048]
    float* out = (float*)d_out;

    cudaFuncSetAttribute(k_gemm, cudaFuncAttributeMaxDynamicSharedMemorySize, GEMM_SMEM);

    k_split<<<17408, 256>>>(feat, Wm);
    k_zero<<<(NVB * D_OUTF) / 256, 256>>>();
    k_gemm<<<dim3(16, 256), 256, GEMM_SMEM>>>();
    k_stats2<<<dim3(D_OUTF / 256, NVB), 256>>>(gamma, beta);
    k_sparsemax<<<B_ROWS, 128>>>(priors, out);
}

// round 8
// speedup vs baseline: 2.0804x; 1.1350x over previous
#include <cuda_runtime.h>
#include <cuda_bf16.h>
#include <cuda_fp16.h>
#include <cstdint>

// ============================================================================
// Problem constants
// ============================================================================
#define B_ROWS 32768
#define D_INF  512
#define D_OUTF 2048
#define VBSZ   256
#define NVB    (B_ROWS / VBSZ)   // 128
#define BN_EPS 1e-5f

// ============================================================================
// Device scratch (static globals; no cudaMalloc allowed)
// ============================================================================
__device__ __half g_A0[(size_t)B_ROWS * D_INF];   // hi fp16 of feat
__device__ __half g_A1[(size_t)B_ROWS * D_INF];   // lo fp16 of feat
__device__ __half g_W0[(size_t)D_OUTF * D_INF];   // fp16 of W
__device__ float  g_x [(size_t)B_ROWS * D_OUTF];  // GEMM result
__device__ float  g_psum [(size_t)NVB * D_OUTF];  // col sums per vb
__device__ float  g_psum2[(size_t)NVB * D_OUTF];  // col sumsq per vb
__device__ float  g_scale[(size_t)NVB * D_OUTF];  // rstd*gamma
__device__ float  g_shift[(size_t)NVB * D_OUTF];  // beta - mean*rstd*gamma

// ============================================================================
// PTX helpers (base ISA only: cp.async + ldmatrix + mma.sync)
// ============================================================================
__device__ __forceinline__ uint32_t smem_to_u32(const void* p) {
    uint32_t a;
    asm("{ .reg .u64 t; cvta.to.shared.u64 t, %1; cvt.u32.u64 %0, t; }" : "=r"(a) : "l"(p));
    return a;
}

#define CP_ASYNC_16(dst_u32, src_ptr) \
    asm volatile("cp.async.cg.shared.global [%0], [%1], 16;" :: "r"(dst_u32), "l"(src_ptr))
#define CP_ASYNC_COMMIT() asm volatile("cp.async.commit_group;" ::: "memory")
#define CP_ASYNC_WAIT_1() asm volatile("cp.async.wait_group 1;" ::: "memory")

#define LDMATRIX_X4(r0, r1, r2, r3, addr) \
    asm volatile("ldmatrix.sync.aligned.m8n8.x4.shared.b16 {%0,%1,%2,%3}, [%4];" \
                 : "=r"(r0), "=r"(r1), "=r"(r2), "=r"(r3) : "r"(addr))

#define MMA_16816(d, a, b0, b1) \
    asm volatile("mma.sync.aligned.m16n8k16.row.col.f32.f16.f16.f32 " \
                 "{%0,%1,%2,%3}, {%4,%5,%6,%7}, {%8,%9}, {%0,%1,%2,%3};" \
                 : "+f"((d)[0]), "+f"((d)[1]), "+f"((d)[2]), "+f"((d)[3]) \
                 : "r"((a)[0]), "r"((a)[1]), "r"((a)[2]), "r"((a)[3]), "r"(b0), "r"(b1))

// ============================================================================
// Kernel 1: split fp32 A -> (fp16 hi, fp16 lo); round W -> fp16
// ============================================================================
__global__ void k_split(const float* __restrict__ feat, const float* __restrict__ Wm) {
    constexpr int NA4 = B_ROWS * D_INF / 4;   // 4194304
    constexpr int NW4 = D_OUTF * D_INF / 4;   // 262144
    int idx = blockIdx.x * blockDim.x + threadIdx.x;
    if (idx < NA4) {
        float4 a = reinterpret_cast<const float4*>(feat)[idx];
        __half hx = __float2half_rn(a.x), hy = __float2half_rn(a.y);
        __half hz = __float2half_rn(a.z), hw = __float2half_rn(a.w);
        __half lx = __float2half_rn(a.x - __half2float(hx));
        __half ly = __float2half_rn(a.y - __half2float(hy));
        __half lz = __float2half_rn(a.z - __half2float(hz));
        __half lw = __float2half_rn(a.w - __half2float(hw));
        __half2 h01 = __halves2half2(hx, hy), h23 = __halves2half2(hz, hw);
        __half2 l01 = __halves2half2(lx, ly), l23 = __halves2half2(lz, lw);
        uint2 hv, lv;
        hv.x = *reinterpret_cast<uint32_t*>(&h01); hv.y = *reinterpret_cast<uint32_t*>(&h23);
        lv.x = *reinterpret_cast<uint32_t*>(&l01); lv.y = *reinterpret_cast<uint32_t*>(&l23);
        *reinterpret_cast<uint2*>(g_A0 + (size_t)idx * 4) = hv;
        *reinterpret_cast<uint2*>(g_A1 + (size_t)idx * 4) = lv;
    } else if (idx < NA4 + NW4) {
        int i = idx - NA4;
        float4 a = reinterpret_cast<const float4*>(Wm)[i];
        __half2 h01 = __floats2half2_rn(a.x, a.y);
        __half2 h23 = __floats2half2_rn(a.z, a.w);
        uint2 hv;
        hv.x = *reinterpret_cast<uint32_t*>(&h01); hv.y = *reinterpret_cast<uint32_t*>(&h23);
        *reinterpret_cast<uint2*>(g_W0 + (size_t)i * 4) = hv;
    }
}

// ============================================================================
// Kernel 1b: zero the stats accumulators (graph replays need fresh zeros)
// ============================================================================
__global__ void k_zero() {
    int i = blockIdx.x * 256 + threadIdx.x;
    g_psum[i] = 0.f;
    g_psum2[i] = 0.f;
}

// ============================================================================
// Kernel 2: GEMM x = A @ W^T, fp16 2-term split (2 MMAs/k-step).
//   CTA 128x128, 256 thr, BK=32, 3-stage cp.async (92KB smem -> 2 CTAs/SM).
//   Epilogue: streaming store of x + GhostBN partial sums via atomics.
// ============================================================================
#define BK        32
#define ROW_PAD   40                       // fp16 per smem row (80 bytes)
#define TILE_B    (128 * ROW_PAD * 2)      // 10240 bytes per 128x32 tile
#define STAGE_B   (3 * TILE_B)             // A0,A1,W0 = 30720 bytes
#define NSTAGE    3
#define GEMM_SMEM (NSTAGE * STAGE_B)       // 92160 bytes -> 2 CTAs/SM
#define KTILES    (D_INF / BK)             // 16

__device__ __forceinline__ void gemm_load_stage(
    uint32_t smem_base, int stage, int m0, int n0, int k0, int tid)
{
    const __half* bases[3] = {
        g_A0 + (size_t)m0 * D_INF + k0,
        g_A1 + (size_t)m0 * D_INF + k0,
        g_W0 + (size_t)n0 * D_INF + k0
    };
    uint32_t sbase = smem_base + stage * STAGE_B;
#pragma unroll
    for (int i = 0; i < 6; i++) {
        int chunk = tid + 256 * i;          // 0..1535
        int tile = chunk >> 9;              // 0..2
        int idx = chunk & 511;
        int row = idx >> 2;
        int seg = idx & 3;
        const __half* src = bases[tile] + (size_t)row * D_INF + seg * 8;
        uint32_t dst = sbase + tile * TILE_B + row * (ROW_PAD * 2) + seg * 16;
        CP_ASYNC_16(dst, src);
    }
}

__global__ void __launch_bounds__(256, 2) k_gemm() {
    extern __shared__ char smem[];
    const uint32_t smem_base = smem_to_u32(smem);
    const int tid = threadIdx.x;
    const int wid = tid >> 5, lid = tid & 31;
    const int m0 = blockIdx.y * 128;
    const int n0 = blockIdx.x * 128;
    const int wm = wid & 1;                 // 0..1 -> m offset 64*wm
    const int wn = wid >> 1;                // 0..3 -> n offset 32*wn

    uint32_t offA[4];
#pragma unroll
    for (int mf = 0; mf < 4; mf++)
        offA[mf] = (uint32_t)((wm * 64 + mf * 16 + (lid & 15)) * (ROW_PAD * 2)
                              + (lid >> 4) * 16);
    uint32_t offB[2];
#pragma unroll
    for (int g = 0; g < 2; g++)
        offB[g] = (uint32_t)((wn * 32 + g * 16 + (lid & 7) + ((lid >> 4) << 3)) * (ROW_PAD * 2)
                             + ((lid >> 3) & 1) * 16);

    float acc[4][4][4];
#pragma unroll
    for (int mf = 0; mf < 4; mf++)
#pragma unroll
        for (int nf = 0; nf < 4; nf++)
#pragma unroll
            for (int r = 0; r < 4; r++) acc[mf][nf][r] = 0.f;

    gemm_load_stage(smem_base, 0, m0, n0, 0, tid);
    CP_ASYNC_COMMIT();
    gemm_load_stage(smem_base, 1, m0, n0, BK, tid);
    CP_ASYNC_COMMIT();

    for (int kt = 0; kt < KTILES; kt++) {
        CP_ASYNC_WAIT_1();                  // stage kt ready
        __syncthreads();

        if (kt + 2 < KTILES)
            gemm_load_stage(smem_base, (kt + 2) % NSTAGE, m0, n0, (kt + 2) * BK, tid);
        CP_ASYNC_COMMIT();

        uint32_t sbase = smem_base + (kt % NSTAGE) * STAGE_B;
        uint32_t sA0 = sbase, sA1 = sbase + TILE_B;
        uint32_t sW0 = sbase + 2 * TILE_B;

#pragma unroll
        for (int kk = 0; kk < 2; kk++) {
            uint32_t koff = kk * 32;

            // Load B frags + A0 frags, run pass 0; then A1 frags, pass 1.
            // (Shortens a1 liveness -> fits 128-reg budget for 2 CTAs/SM.)
            uint32_t b0[2][4];
#pragma unroll
            for (int g = 0; g < 2; g++)
                LDMATRIX_X4(b0[g][0], b0[g][1], b0[g][2], b0[g][3], sW0 + offB[g] + koff);

            uint32_t a0[4][4];
#pragma unroll
            for (int mf = 0; mf < 4; mf++)
                LDMATRIX_X4(a0[mf][0], a0[mf][1], a0[mf][2], a0[mf][3], sA0 + offA[mf] + koff);
#pragma unroll
            for (int mf = 0; mf < 4; mf++)
#pragma unroll
                for (int nf = 0; nf < 4; nf++) {
                    int g = nf >> 1, p = (nf & 1) * 2;
                    MMA_16816(acc[mf][nf], a0[mf], b0[g][p], b0[g][p + 1]);
                }

            uint32_t a1[4][4];
#pragma unroll
            for (int mf = 0; mf < 4; mf++)
                LDMATRIX_X4(a1[mf][0], a1[mf][1], a1[mf][2], a1[mf][3], sA1 + offA[mf] + koff);
#pragma unroll
            for (int mf = 0; mf < 4; mf++)
#pragma unroll
                for (int nf = 0; nf < 4; nf++) {
                    int g = nf >> 1, p = (nf & 1) * 2;
                    MMA_16816(acc[mf][nf], a1[mf], b0[g][p], b0[g][p + 1]);
                }
        }
        __syncthreads();
    }

    // ---- Epilogue: store x (streaming) ----
    const int rbase = m0 + wm * 64 + (lid >> 2);
    const int cbase = n0 + wn * 32 + (lid & 3) * 2;
#pragma unroll
    for (int mf = 0; mf < 4; mf++) {
#pragma unroll
        for (int nf = 0; nf < 4; nf++) {
            int r0 = rbase + mf * 16;
            int c = cbase + nf * 8;
            float2 v0 = make_float2(acc[mf][nf][0], acc[mf][nf][1]);
            float2 v1 = make_float2(acc[mf][nf][2], acc[mf][nf][3]);
            __stcs(reinterpret_cast<float2*>(g_x + (size_t)r0 * D_OUTF + c), v0);
            __stcs(reinterpret_cast<float2*>(g_x + (size_t)(r0 + 8) * D_OUTF + c), v1);
        }
    }

    // ---- Epilogue: GhostBN partial sums (warp: 64 rows x 32 cols; vb = m0>>8)
    float s[8], q[8];
#pragma unroll
    for (int nf = 0; nf < 4; nf++) {
#pragma unroll
        for (int w = 0; w < 2; w++) {
            float ss = 0.f, qq = 0.f;
#pragma unroll
            for (int mf = 0; mf < 4; mf++) {
                float v0 = acc[mf][nf][w], v1 = acc[mf][nf][w + 2];
                ss += v0 + v1;
                qq = fmaf(v0, v0, qq);
                qq = fmaf(v1, v1, qq);
            }
            s[nf * 2 + w] = ss;
            q[nf * 2 + w] = qq;
        }
    }
#pragma unroll
    for (int o = 4; o < 32; o <<= 1) {
#pragma unroll
        for (int t = 0; t < 8; t++) {
            s[t] += __shfl_xor_sync(0xffffffffu, s[t], o);
            q[t] += __shfl_xor_sync(0xffffffffu, q[t], o);
        }
    }
    if ((lid >> 2) == 0) {
        const int vb = m0 >> 8;
        float* ps = g_psum  + (size_t)vb * D_OUTF;
        float* pq = g_psum2 + (size_t)vb * D_OUTF;
#pragma unroll
        for (int nf = 0; nf < 4; nf++) {
#pragma unroll
            for (int w = 0; w < 2; w++) {
                int c = cbase + nf * 8 + w;
                atomicAdd(ps + c, s[nf * 2 + w]);
                atomicAdd(pq + c, q[nf * 2 + w]);
            }
        }
    }
}

// ============================================================================
// Kernel 3: fold partial sums -> scale/shift per (vb, d)
// ============================================================================
__global__ void k_stats2(const float* __restrict__ gamma, const float* __restrict__ beta) {
    int d = blockIdx.x * 256 + threadIdx.x;
    int vb = blockIdx.y;
    size_t i = (size_t)vb * D_OUTF + d;
    float sm = g_psum[i], sq = g_psum2[i];
    float mean = sm * (1.f / VBSZ);
    float var = fmaxf(sq * (1.f / VBSZ) - mean * mean, 0.f);
    float rstd = rsqrtf(var + BN_EPS);
    float sc = rstd * gamma[d];
    g_scale[i] = sc;
    g_shift[i] = beta[d] - mean * sc;
}

// ============================================================================
// Kernel 4: fused BN*prior + sparsemax. ONE 128-thread block per row,
//   z[16]/lane. Newton on f(tau)=sum(max(z-tau,0))-1 from tau0=max-1, x10.
// ============================================================================
__global__ void __launch_bounds__(128) k_sparsemax(const float* __restrict__ priors,
                                                   float* __restrict__ out) {
    __shared__ float  s_max[4];
    __shared__ float2 s_red[2][4];
    const int tid = threadIdx.x;
    const int wid = tid >> 5, lid = tid & 31;
    const int row = blockIdx.x;
    const int vb = row >> 8;

    const float4* xv = reinterpret_cast<const float4*>(g_x + (size_t)row * D_OUTF);
    const float4* pv = reinterpret_cast<const float4*>(priors + (size_t)row * D_OUTF);
    const float4* sv = reinterpret_cast<const float4*>(g_scale + (size_t)vb * D_OUTF);
    const float4* hv = reinterpret_cast<const float4*>(g_shift + (size_t)vb * D_OUTF);

    float z[16];
#pragma unroll
    for (int j = 0; j < 4; j++) {
        int c = tid + 128 * j;
        float4 x = __ldcs(xv + c);
        float4 p = __ldcs(pv + c);
        float4 sc = sv[c];
        float4 sh = hv[c];
        z[4 * j + 0] = fmaf(x.x, sc.x, sh.x) * p.x;
        z[4 * j + 1] = fmaf(x.y, sc.y, sh.y) * p.y;
        z[4 * j + 2] = fmaf(x.z, sc.z, sh.z) * p.z;
        z[4 * j + 3] = fmaf(x.w, sc.w, sh.w) * p.w;
    }

    float m = z[0];
#pragma unroll
    for (int i = 1; i < 16; i++) m = fmaxf(m, z[i]);
#pragma unroll
    for (int o = 16; o; o >>= 1) m = fmaxf(m, __shfl_xor_sync(0xffffffffu, m, o));
    if (lid == 0) s_max[wid] = m;
    __syncthreads();
    m = fmaxf(fmaxf(s_max[0], s_max[1]), fmaxf(s_max[2], s_max[3]));

    float tau = m - 1.f;
#pragma unroll 1
    for (int it = 0; it < 10; it++) {
        float S = 0.f, C = 0.f;
#pragma unroll
        for (int i = 0; i < 16; i++) {
            if (z[i] > tau) { S += z[i]; C += 1.f; }
        }
#pragma unroll
        for (int o = 16; o; o >>= 1) {
            S += __shfl_xor_sync(0xffffffffu, S, o);
            C += __shfl_xor_sync(0xffffffffu, C, o);
        }
        if (lid == 0) s_red[it & 1][wid] = make_float2(S, C);
        __syncthreads();
        float2 r0 = s_red[it & 1][0], r1 = s_red[it & 1][1];
        float2 r2 = s_red[it & 1][2], r3 = s_red[it & 1][3];
        tau = (r0.x + r1.x + r2.x + r3.x - 1.f) / (r0.y + r1.y + r2.y + r3.y);
    }

    float4* ov = reinterpret_cast<float4*>(out + (size_t)row * D_OUTF);
#pragma unroll
    for (int j = 0; j < 4; j++) {
        int c = tid + 128 * j;
        float4 v;
        v.x = fmaxf(z[4 * j + 0] - tau, 0.f);
        v.y = fmaxf(z[4 * j + 1] - tau, 0.f);
        v.z = fmaxf(z[4 * j + 2] - tau, 0.f);
        v.w = fmaxf(z[4 * j + 3] - tau, 0.f);
        __stcs(ov + c, v);
    }
}

// ============================================================================
// Launch
// ============================================================================
extern "C" void kernel_launch(void* const* d_in, const int* in_sizes, int n_in,
                              void* d_out, int out_size) {
    const float* priors = (const float*)d_in[0];   // [32768, 2048]
    const float* feat   = (const float*)d_in[1];   // [32768, 512]
    const float* Wm     = (const float*)d_in[2];   // [2048, 512]
    const float* gamma  = (const float*)d_in[3];   // [2048]
    const float* beta   = (const float*)d_in[4];   // [2048]
    float* out = (float*)d_out;

    cudaFuncSetAttribute(k_gemm, cudaFuncAttributeMaxDynamicSharedMemorySize, GEMM_SMEM);

    k_split<<<17408, 256>>>(feat, Wm);
    k_zero<<<(NVB * D_OUTF) / 256, 256>>>();
    k_gemm<<<dim3(16, 256), 256, GEMM_SMEM>>>();
    k_stats2<<<dim3(D_OUTF / 256, NVB), 256>>>(gamma, beta);
    k_sparsemax<<<B_ROWS, 128>>>(priors, out);
}

// round 11
// speedup vs baseline: 2.6496x; 1.2736x over previous
#include <cuda_runtime.h>
#include <cuda_bf16.h>
#include <cuda_fp16.h>
#include <cstdint>

// ============================================================================
// Problem constants
// ============================================================================
#define B_ROWS 32768
#define D_INF  512
#define D_OUTF 2048
#define VBSZ   256
#define NVB    (B_ROWS / VBSZ)   // 128
#define BN_EPS 1e-5f

// ============================================================================
// Device scratch (static globals; no cudaMalloc allowed)
// ============================================================================
__device__ __half g_A0[(size_t)B_ROWS * D_INF];   // fp16 of feat
__device__ __half g_W0[(size_t)D_OUTF * D_INF];   // fp16 of W
__device__ float  g_x [(size_t)B_ROWS * D_OUTF];  // GEMM result
__device__ float  g_psum [(size_t)NVB * D_OUTF];  // col sums per vb
__device__ float  g_psum2[(size_t)NVB * D_OUTF];  // col sumsq per vb
__device__ float  g_scale[(size_t)NVB * D_OUTF];  // rstd*gamma
__device__ float  g_shift[(size_t)NVB * D_OUTF];  // beta - mean*rstd*gamma

// ============================================================================
// PTX helpers (base ISA only: cp.async + ldmatrix + mma.sync)
// ============================================================================
__device__ __forceinline__ uint32_t smem_to_u32(const void* p) {
    uint32_t a;
    asm("{ .reg .u64 t; cvta.to.shared.u64 t, %1; cvt.u32.u64 %0, t; }" : "=r"(a) : "l"(p));
    return a;
}

#define CP_ASYNC_16(dst_u32, src_ptr) \
    asm volatile("cp.async.cg.shared.global [%0], [%1], 16;" :: "r"(dst_u32), "l"(src_ptr))
#define CP_ASYNC_COMMIT() asm volatile("cp.async.commit_group;" ::: "memory")
#define CP_ASYNC_WAIT_2() asm volatile("cp.async.wait_group 2;" ::: "memory")

#define LDMATRIX_X4(r0, r1, r2, r3, addr) \
    asm volatile("ldmatrix.sync.aligned.m8n8.x4.shared.b16 {%0,%1,%2,%3}, [%4];" \
                 : "=r"(r0), "=r"(r1), "=r"(r2), "=r"(r3) : "r"(addr))

#define MMA_16816(d, a, b0, b1) \
    asm volatile("mma.sync.aligned.m16n8k16.row.col.f32.f16.f16.f32 " \
                 "{%0,%1,%2,%3}, {%4,%5,%6,%7}, {%8,%9}, {%0,%1,%2,%3};" \
                 : "+f"((d)[0]), "+f"((d)[1]), "+f"((d)[2]), "+f"((d)[3]) \
                 : "r"((a)[0]), "r"((a)[1]), "r"((a)[2]), "r"((a)[3]), "r"(b0), "r"(b1))

// ============================================================================
// Kernel 1: round fp32 A and W -> fp16
// ============================================================================
__global__ void k_split(const float* __restrict__ feat, const float* __restrict__ Wm) {
    constexpr int NA4 = B_ROWS * D_INF / 4;   // 4194304
    constexpr int NW4 = D_OUTF * D_INF / 4;   // 262144
    int idx = blockIdx.x * blockDim.x + threadIdx.x;
    const float* src;
    __half* dst;
    int i;
    if (idx < NA4) { src = feat; dst = g_A0; i = idx; }
    else if (idx < NA4 + NW4) { src = Wm; dst = g_W0; i = idx - NA4; }
    else return;

    float4 a = reinterpret_cast<const float4*>(src)[i];
    __half2 h01 = __floats2half2_rn(a.x, a.y);
    __half2 h23 = __floats2half2_rn(a.z, a.w);
    uint2 hv;
    hv.x = *reinterpret_cast<uint32_t*>(&h01);
    hv.y = *reinterpret_cast<uint32_t*>(&h23);
    *reinterpret_cast<uint2*>(dst + (size_t)i * 4) = hv;
}

// ============================================================================
// Kernel 1b: zero the stats accumulators (graph replays need fresh zeros)
// ============================================================================
__global__ void k_zero() {
    int i = blockIdx.x * 256 + threadIdx.x;
    g_psum[i] = 0.f;
    g_psum2[i] = 0.f;
}

// ============================================================================
// Kernel 2: GEMM x = A @ W^T, single fp16 term (16 MMAs per kk).
//   CTA 128x128, 256 thr, BK=32, 4-stage cp.async (80KB smem -> 2 CTAs/SM).
//   Epilogue: streaming store of x + GhostBN partial sums via atomics.
// ============================================================================
#define BK        32
#define ROW_PAD   40                       // fp16 per smem row (80 bytes)
#define TILE_B    (128 * ROW_PAD * 2)      // 10240 bytes per 128x32 tile
#define STAGE_B   (2 * TILE_B)             // A0,W0 = 20480 bytes
#define NSTAGE    4
#define GEMM_SMEM (NSTAGE * STAGE_B)       // 81920 bytes -> 2 CTAs/SM
#define KTILES    (D_INF / BK)             // 16

__device__ __forceinline__ void gemm_load_stage(
    uint32_t smem_base, int stage, int m0, int n0, int k0, int tid)
{
    const __half* bases[2] = {
        g_A0 + (size_t)m0 * D_INF + k0,
        g_W0 + (size_t)n0 * D_INF + k0
    };
    uint32_t sbase = smem_base + stage * STAGE_B;
#pragma unroll
    for (int i = 0; i < 4; i++) {
        int chunk = tid + 256 * i;          // 0..1023
        int tile = chunk >> 9;              // 0..1
        int idx = chunk & 511;
        int row = idx >> 2;
        int seg = idx & 3;
        const __half* src = bases[tile] + (size_t)row * D_INF + seg * 8;
        uint32_t dst = sbase + tile * TILE_B + row * (ROW_PAD * 2) + seg * 16;
        CP_ASYNC_16(dst, src);
    }
}

__global__ void __launch_bounds__(256, 2) k_gemm() {
    extern __shared__ char smem[];
    const uint32_t smem_base = smem_to_u32(smem);
    const int tid = threadIdx.x;
    const int wid = tid >> 5, lid = tid & 31;
    const int m0 = blockIdx.y * 128;
    const int n0 = blockIdx.x * 128;
    const int wm = wid & 1;                 // 0..1 -> m offset 64*wm
    const int wn = wid >> 1;                // 0..3 -> n offset 32*wn

    uint32_t offA[4];
#pragma unroll
    for (int mf = 0; mf < 4; mf++)
        offA[mf] = (uint32_t)((wm * 64 + mf * 16 + (lid & 15)) * (ROW_PAD * 2)
                              + (lid >> 4) * 16);
    uint32_t offB[2];
#pragma unroll
    for (int g = 0; g < 2; g++)
        offB[g] = (uint32_t)((wn * 32 + g * 16 + (lid & 7) + ((lid >> 4) << 3)) * (ROW_PAD * 2)
                             + ((lid >> 3) & 1) * 16);

    float acc[4][4][4];
#pragma unroll
    for (int mf = 0; mf < 4; mf++)
#pragma unroll
        for (int nf = 0; nf < 4; nf++)
#pragma unroll
            for (int r = 0; r < 4; r++) acc[mf][nf][r] = 0.f;

    gemm_load_stage(smem_base, 0, m0, n0, 0, tid);
    CP_ASYNC_COMMIT();
    gemm_load_stage(smem_base, 1, m0, n0, BK, tid);
    CP_ASYNC_COMMIT();
    gemm_load_stage(smem_base, 2, m0, n0, 2 * BK, tid);
    CP_ASYNC_COMMIT();

    for (int kt = 0; kt < KTILES; kt++) {
        CP_ASYNC_WAIT_2();                  // stage kt ready
        __syncthreads();

        if (kt + 3 < KTILES)
            gemm_load_stage(smem_base, (kt + 3) % NSTAGE, m0, n0, (kt + 3) * BK, tid);
        CP_ASYNC_COMMIT();

        uint32_t sbase = smem_base + (kt % NSTAGE) * STAGE_B;
        uint32_t sA0 = sbase;
        uint32_t sW0 = sbase + TILE_B;

#pragma unroll
        for (int kk = 0; kk < 2; kk++) {
            uint32_t koff = kk * 32;

            uint32_t b0[2][4];
#pragma unroll
            for (int g = 0; g < 2; g++)
                LDMATRIX_X4(b0[g][0], b0[g][1], b0[g][2], b0[g][3], sW0 + offB[g] + koff);

            uint32_t a0[4][4];
#pragma unroll
            for (int mf = 0; mf < 4; mf++)
                LDMATRIX_X4(a0[mf][0], a0[mf][1], a0[mf][2], a0[mf][3], sA0 + offA[mf] + koff);

#pragma unroll
            for (int mf = 0; mf < 4; mf++)
#pragma unroll
                for (int nf = 0; nf < 4; nf++) {
                    int g = nf >> 1, p = (nf & 1) * 2;
                    MMA_16816(acc[mf][nf], a0[mf], b0[g][p], b0[g][p + 1]);
                }
        }
        __syncthreads();
    }

    // ---- Epilogue: store x (streaming) ----
    const int rbase = m0 + wm * 64 + (lid >> 2);
    const int cbase = n0 + wn * 32 + (lid & 3) * 2;
#pragma unroll
    for (int mf = 0; mf < 4; mf++) {
#pragma unroll
        for (int nf = 0; nf < 4; nf++) {
            int r0 = rbase + mf * 16;
            int c = cbase + nf * 8;
            float2 v0 = make_float2(acc[mf][nf][0], acc[mf][nf][1]);
            float2 v1 = make_float2(acc[mf][nf][2], acc[mf][nf][3]);
            __stcs(reinterpret_cast<float2*>(g_x + (size_t)r0 * D_OUTF + c), v0);
            __stcs(reinterpret_cast<float2*>(g_x + (size_t)(r0 + 8) * D_OUTF + c), v1);
        }
    }

    // ---- Epilogue: GhostBN partial sums (warp: 64 rows x 32 cols; vb = m0>>8)
    float s[8], q[8];
#pragma unroll
    for (int nf = 0; nf < 4; nf++) {
#pragma unroll
        for (int w = 0; w < 2; w++) {
            float ss = 0.f, qq = 0.f;
#pragma unroll
            for (int mf = 0; mf < 4; mf++) {
                float v0 = acc[mf][nf][w], v1 = acc[mf][nf][w + 2];
                ss += v0 + v1;
                qq = fmaf(v0, v0, qq);
                qq = fmaf(v1, v1, qq);
            }
            s[nf * 2 + w] = ss;
            q[nf * 2 + w] = qq;
        }
    }
#pragma unroll
    for (int o = 4; o < 32; o <<= 1) {
#pragma unroll
        for (int t = 0; t < 8; t++) {
            s[t] += __shfl_xor_sync(0xffffffffu, s[t], o);
            q[t] += __shfl_xor_sync(0xffffffffu, q[t], o);
        }
    }
    if ((lid >> 2) == 0) {
        const int vb = m0 >> 8;
        float* ps = g_psum  + (size_t)vb * D_OUTF;
        float* pq = g_psum2 + (size_t)vb * D_OUTF;
#pragma unroll
        for (int nf = 0; nf < 4; nf++) {
#pragma unroll
            for (int w = 0; w < 2; w++) {
                int c = cbase + nf * 8 + w;
                atomicAdd(ps + c, s[nf * 2 + w]);
                atomicAdd(pq + c, q[nf * 2 + w]);
            }
        }
    }
}

// ============================================================================
// Kernel 3: fold partial sums -> scale/shift per (vb, d)
// ============================================================================
__global__ void k_stats2(const float* __restrict__ gamma, const float* __restrict__ beta) {
    int d = blockIdx.x * 256 + threadIdx.x;
    int vb = blockIdx.y;
    size_t i = (size_t)vb * D_OUTF + d;
    float sm = g_psum[i], sq = g_psum2[i];
    float mean = sm * (1.f / VBSZ);
    float var = fmaxf(sq * (1.f / VBSZ) - mean * mean, 0.f);
    float rstd = rsqrtf(var + BN_EPS);
    float sc = rstd * gamma[d];
    g_scale[i] = sc;
    g_shift[i] = beta[d] - mean * sc;
}

// ============================================================================
// Kernel 4: fused BN*prior + sparsemax. 256-thread block = 2 rows
//   (128 threads/row, z[16]/lane). Newton on f(tau)=sum(max(z-tau,0))-1
//   from tau0=max-1, x10 iters.
// ============================================================================
__global__ void __launch_bounds__(256) k_sparsemax(const float* __restrict__ priors,
                                                   float* __restrict__ out) {
    __shared__ float  s_max[2][4];
    __shared__ float2 s_red[2][2][4];       // [buf][rslot][warp]
    const int tid = threadIdx.x;
    const int rslot = tid >> 7;             // 0/1: which row of this block
    const int t = tid & 127;
    const int wid = t >> 5, lid = tid & 31;
    const int row = blockIdx.x * 2 + rslot;
    const int vb = row >> 8;

    const float4* xv = reinterpret_cast<const float4*>(g_x + (size_t)row * D_OUTF);
    const float4* pv = reinterpret_cast<const float4*>(priors + (size_t)row * D_OUTF);
    const float4* sv = reinterpret_cast<const float4*>(g_scale + (size_t)vb * D_OUTF);
    const float4* hv = reinterpret_cast<const float4*>(g_shift + (size_t)vb * D_OUTF);

    float z[16];
#pragma unroll
    for (int j = 0; j < 4; j++) {
        int c = t + 128 * j;
        float4 x = __ldcs(xv + c);
        float4 p = __ldcs(pv + c);
        float4 sc = sv[c];
        float4 sh = hv[c];
        z[4 * j + 0] = fmaf(x.x, sc.x, sh.x) * p.x;
        z[4 * j + 1] = fmaf(x.y, sc.y, sh.y) * p.y;
        z[4 * j + 2] = fmaf(x.z, sc.z, sh.z) * p.z;
        z[4 * j + 3] = fmaf(x.w, sc.w, sh.w) * p.w;
    }

    float m = z[0];
#pragma unroll
    for (int i = 1; i < 16; i++) m = fmaxf(m, z[i]);
#pragma unroll
    for (int o = 16; o; o >>= 1) m = fmaxf(m, __shfl_xor_sync(0xffffffffu, m, o));
    if (lid == 0) s_max[rslot][wid] = m;
    __syncthreads();
    m = fmaxf(fmaxf(s_max[rslot][0], s_max[rslot][1]),
              fmaxf(s_max[rslot][2], s_max[rslot][3]));

    float tau = m - 1.f;
#pragma unroll 1
    for (int it = 0; it < 10; it++) {
        float S = 0.f, C = 0.f;
#pragma unroll
        for (int i = 0; i < 16; i++) {
            if (z[i] > tau) { S += z[i]; C += 1.f; }
        }
#pragma unroll
        for (int o = 16; o; o >>= 1) {
            S += __shfl_xor_sync(0xffffffffu, S, o);
            C += __shfl_xor_sync(0xffffffffu, C, o);
        }
        if (lid == 0) s_red[it & 1][rslot][wid] = make_float2(S, C);
        __syncthreads();
        float2 r0 = s_red[it & 1][rslot][0], r1 = s_red[it & 1][rslot][1];
        float2 r2 = s_red[it & 1][rslot][2], r3 = s_red[it & 1][rslot][3];
        tau = (r0.x + r1.x + r2.x + r3.x - 1.f) / (r0.y + r1.y + r2.y + r3.y);
    }

    float4* ov = reinterpret_cast<float4*>(out + (size_t)row * D_OUTF);
#pragma unroll
    for (int j = 0; j < 4; j++) {
        int c = t + 128 * j;
        float4 v;
        v.x = fmaxf(z[4 * j + 0] - tau, 0.f);
        v.y = fmaxf(z[4 * j + 1] - tau, 0.f);
        v.z = fmaxf(z[4 * j + 2] - tau, 0.f);
        v.w = fmaxf(z[4 * j + 3] - tau, 0.f);
        __stcs(ov + c, v);
    }
}

// ============================================================================
// Launch
// ============================================================================
extern "C" void kernel_launch(void* const* d_in, const int* in_sizes, int n_in,
                              void* d_out, int out_size) {
    const float* priors = (const float*)d_in[0];   // [32768, 2048]
    const float* feat   = (const float*)d_in[1];   // [32768, 512]
    const float* Wm     = (const float*)d_in[2];   // [2048, 512]
    const float* gamma  = (const float*)d_in[3];   // [2048]
    const float* beta   = (const float*)d_in[4];   // [2048]
    float* out = (float*)d_out;

    cudaFuncSetAttribute(k_gemm, cudaFuncAttributeMaxDynamicSharedMemorySize, GEMM_SMEM);

    k_split<<<17408, 256>>>(feat, Wm);
    k_zero<<<(NVB * D_OUTF) / 256, 256>>>();
    k_gemm<<<dim3(16, 256), 256, GEMM_SMEM>>>();
    k_stats2<<<dim3(D_OUTF / 256, NVB), 256>>>(gamma, beta);
    k_sparsemax<<<B_ROWS / 2, 256>>>(priors, out);
}

// round 14
// speedup vs baseline: 2.8558x; 1.0779x over previous
#include <cuda_runtime.h>
#include <cuda_bf16.h>
#include <cuda_fp16.h>
#include <cstdint>

// ============================================================================
// Problem constants
// ============================================================================
#define B_ROWS 32768
#define D_INF  512
#define D_OUTF 2048
#define VBSZ   256
#define NVB    (B_ROWS / VBSZ)   // 128
#define BN_EPS 1e-5f

// ============================================================================
// Device scratch (static globals; no cudaMalloc allowed)
// ============================================================================
__device__ __half g_A0[(size_t)B_ROWS * D_INF];   // fp16 of feat
__device__ __half g_W0[(size_t)D_OUTF * D_INF];   // fp16 of W
__device__ float  g_x [(size_t)B_ROWS * D_OUTF];  // GEMM result
__device__ float  g_psum [(size_t)NVB * D_OUTF];  // col sums per vb
__device__ float  g_psum2[(size_t)NVB * D_OUTF];  // col sumsq per vb
__device__ float  g_scale[(size_t)NVB * D_OUTF];  // rstd*gamma
__device__ float  g_shift[(size_t)NVB * D_OUTF];  // beta - mean*rstd*gamma

// ============================================================================
// PTX helpers (base ISA only: cp.async + ldmatrix + mma.sync)
// ============================================================================
__device__ __forceinline__ uint32_t smem_to_u32(const void* p) {
    uint32_t a;
    asm("{ .reg .u64 t; cvta.to.shared.u64 t, %1; cvt.u32.u64 %0, t; }" : "=r"(a) : "l"(p));
    return a;
}

#define CP_ASYNC_16(dst_u32, src_ptr) \
    asm volatile("cp.async.cg.shared.global [%0], [%1], 16;" :: "r"(dst_u32), "l"(src_ptr))
#define CP_ASYNC_COMMIT() asm volatile("cp.async.commit_group;" ::: "memory")
#define CP_ASYNC_WAIT_3() asm volatile("cp.async.wait_group 3;" ::: "memory")

#define LDMATRIX_X4(r0, r1, r2, r3, addr) \
    asm volatile("ldmatrix.sync.aligned.m8n8.x4.shared.b16 {%0,%1,%2,%3}, [%4];" \
                 : "=r"(r0), "=r"(r1), "=r"(r2), "=r"(r3) : "r"(addr))

#define MMA_16816(d, a, b0, b1) \
    asm volatile("mma.sync.aligned.m16n8k16.row.col.f32.f16.f16.f32 " \
                 "{%0,%1,%2,%3}, {%4,%5,%6,%7}, {%8,%9}, {%0,%1,%2,%3};" \
                 : "+f"((d)[0]), "+f"((d)[1]), "+f"((d)[2]), "+f"((d)[3]) \
                 : "r"((a)[0]), "r"((a)[1]), "r"((a)[2]), "r"((a)[3]), "r"(b0), "r"(b1))

// ============================================================================
// Kernel 1: round fp32 A and W -> fp16; tail blocks zero the stats buffers
// ============================================================================
__global__ void k_split(const float* __restrict__ feat, const float* __restrict__ Wm) {
    constexpr int NA4 = B_ROWS * D_INF / 4;   // 4194304
    constexpr int NW4 = D_OUTF * D_INF / 4;   // 262144
    constexpr int NZ4 = NVB * D_OUTF / 4;     // 65536
    int idx = blockIdx.x * blockDim.x + threadIdx.x;
    if (idx < NA4 + NW4) {
        const float* src;
        __half* dst;
        int i;
        if (idx < NA4) { src = feat; dst = g_A0; i = idx; }
        else { src = Wm; dst = g_W0; i = idx - NA4; }
        float4 a = reinterpret_cast<const float4*>(src)[i];
        __half2 h01 = __floats2half2_rn(a.x, a.y);
        __half2 h23 = __floats2half2_rn(a.z, a.w);
        uint2 hv;
        hv.x = *reinterpret_cast<uint32_t*>(&h01);
        hv.y = *reinterpret_cast<uint32_t*>(&h23);
        *reinterpret_cast<uint2*>(dst + (size_t)i * 4) = hv;
    } else if (idx < NA4 + NW4 + NZ4) {
        int i = idx - (NA4 + NW4);
        float4 zz = make_float4(0.f, 0.f, 0.f, 0.f);
        reinterpret_cast<float4*>(g_psum)[i] = zz;
        reinterpret_cast<float4*>(g_psum2)[i] = zz;
    }
}

// ============================================================================
// Kernel 2: GEMM x = A @ W^T, single fp16 term (16 MMAs per kk).
//   CTA 128x128, 256 thr, BK=32, 5-stage cp.async (100KB smem -> 2 CTAs/SM),
//   ONE barrier per k-tile (5-stage distance makes the bottom sync redundant).
//   Epilogue: streaming store of x + GhostBN partial sums via atomics.
// ============================================================================
#define BK        32
#define ROW_PAD   40                       // fp16 per smem row (80 bytes)
#define TILE_B    (128 * ROW_PAD * 2)      // 10240 bytes per 128x32 tile
#define STAGE_B   (2 * TILE_B)             // A0,W0 = 20480 bytes
#define NSTAGE    5
#define GEMM_SMEM (NSTAGE * STAGE_B)       // 102400 bytes -> 2 CTAs/SM
#define KTILES    (D_INF / BK)             // 16

__device__ __forceinline__ void gemm_load_stage(
    uint32_t smem_base, int stage, int m0, int n0, int k0, int tid)
{
    const __half* bases[2] = {
        g_A0 + (size_t)m0 * D_INF + k0,
        g_W0 + (size_t)n0 * D_INF + k0
    };
    uint32_t sbase = smem_base + stage * STAGE_B;
#pragma unroll
    for (int i = 0; i < 4; i++) {
        int chunk = tid + 256 * i;          // 0..1023
        int tile = chunk >> 9;              // 0..1
        int idx = chunk & 511;
        int row = idx >> 2;
        int seg = idx & 3;
        const __half* src = bases[tile] + (size_t)row * D_INF + seg * 8;
        uint32_t dst = sbase + tile * TILE_B + row * (ROW_PAD * 2) + seg * 16;
        CP_ASYNC_16(dst, src);
    }
}

__global__ void __launch_bounds__(256, 2) k_gemm() {
    extern __shared__ char smem[];
    const uint32_t smem_base = smem_to_u32(smem);
    const int tid = threadIdx.x;
    const int wid = tid >> 5, lid = tid & 31;
    const int m0 = blockIdx.y * 128;
    const int n0 = blockIdx.x * 128;
    const int wm = wid & 1;                 // 0..1 -> m offset 64*wm
    const int wn = wid >> 1;                // 0..3 -> n offset 32*wn

    uint32_t offA[4];
#pragma unroll
    for (int mf = 0; mf < 4; mf++)
        offA[mf] = (uint32_t)((wm * 64 + mf * 16 + (lid & 15)) * (ROW_PAD * 2)
                              + (lid >> 4) * 16);
    uint32_t offB[2];
#pragma unroll
    for (int g = 0; g < 2; g++)
        offB[g] = (uint32_t)((wn * 32 + g * 16 + (lid & 7) + ((lid >> 4) << 3)) * (ROW_PAD * 2)
                             + ((lid >> 3) & 1) * 16);

    float acc[4][4][4];
#pragma unroll
    for (int mf = 0; mf < 4; mf++)
#pragma unroll
        for (int nf = 0; nf < 4; nf++)
#pragma unroll
            for (int r = 0; r < 4; r++) acc[mf][nf][r] = 0.f;

    // Prologue: 4 stages in flight
#pragma unroll
    for (int s = 0; s < 4; s++) {
        gemm_load_stage(smem_base, s, m0, n0, s * BK, tid);
        CP_ASYNC_COMMIT();
    }

    int stage_rd = 0, stage_wr = 4;
    for (int kt = 0; kt < KTILES; kt++) {
        CP_ASYNC_WAIT_3();                  // stage kt landed (<=3 groups pending)
        __syncthreads();                    // single barrier per k-tile

        if (kt + 4 < KTILES)
            gemm_load_stage(smem_base, stage_wr, m0, n0, (kt + 4) * BK, tid);
        CP_ASYNC_COMMIT();
        if (++stage_wr == NSTAGE) stage_wr = 0;

        uint32_t sbase = smem_base + stage_rd * STAGE_B;
        if (++stage_rd == NSTAGE) stage_rd = 0;
        uint32_t sA0 = sbase;
        uint32_t sW0 = sbase + TILE_B;

#pragma unroll
        for (int kk = 0; kk < 2; kk++) {
            uint32_t koff = kk * 32;

            uint32_t b0[2][4];
#pragma unroll
            for (int g = 0; g < 2; g++)
                LDMATRIX_X4(b0[g][0], b0[g][1], b0[g][2], b0[g][3], sW0 + offB[g] + koff);

            uint32_t a0[4][4];
#pragma unroll
            for (int mf = 0; mf < 4; mf++)
                LDMATRIX_X4(a0[mf][0], a0[mf][1], a0[mf][2], a0[mf][3], sA0 + offA[mf] + koff);

#pragma unroll
            for (int mf = 0; mf < 4; mf++)
#pragma unroll
                for (int nf = 0; nf < 4; nf++) {
                    int g = nf >> 1, p = (nf & 1) * 2;
                    MMA_16816(acc[mf][nf], a0[mf], b0[g][p], b0[g][p + 1]);
                }
        }
    }

    // ---- Epilogue: store x (streaming) ----
    const int rbase = m0 + wm * 64 + (lid >> 2);
    const int cbase = n0 + wn * 32 + (lid & 3) * 2;
#pragma unroll
    for (int mf = 0; mf < 4; mf++) {
#pragma unroll
        for (int nf = 0; nf < 4; nf++) {
            int r0 = rbase + mf * 16;
            int c = cbase + nf * 8;
            float2 v0 = make_float2(acc[mf][nf][0], acc[mf][nf][1]);
            float2 v1 = make_float2(acc[mf][nf][2], acc[mf][nf][3]);
            __stcs(reinterpret_cast<float2*>(g_x + (size_t)r0 * D_OUTF + c), v0);
            __stcs(reinterpret_cast<float2*>(g_x + (size_t)(r0 + 8) * D_OUTF + c), v1);
        }
    }

    // ---- Epilogue: GhostBN partial sums (warp: 64 rows x 32 cols; vb = m0>>8)
    float s[8], q[8];
#pragma unroll
    for (int nf = 0; nf < 4; nf++) {
#pragma unroll
        for (int w = 0; w < 2; w++) {
            float ss = 0.f, qq = 0.f;
#pragma unroll
            for (int mf = 0; mf < 4; mf++) {
                float v0 = acc[mf][nf][w], v1 = acc[mf][nf][w + 2];
                ss += v0 + v1;
                qq = fmaf(v0, v0, qq);
                qq = fmaf(v1, v1, qq);
            }
            s[nf * 2 + w] = ss;
            q[nf * 2 + w] = qq;
        }
    }
#pragma unroll
    for (int o = 4; o < 32; o <<= 1) {
#pragma unroll
        for (int t = 0; t < 8; t++) {
            s[t] += __shfl_xor_sync(0xffffffffu, s[t], o);
            q[t] += __shfl_xor_sync(0xffffffffu, q[t], o);
        }
    }
    if ((lid >> 2) == 0) {
        const int vb = m0 >> 8;
        float* ps = g_psum  + (size_t)vb * D_OUTF;
        float* pq = g_psum2 + (size_t)vb * D_OUTF;
#pragma unroll
        for (int nf = 0; nf < 4; nf++) {
#pragma unroll
            for (int w = 0; w < 2; w++) {
                int c = cbase + nf * 8 + w;
                atomicAdd(ps + c, s[nf * 2 + w]);
                atomicAdd(pq + c, q[nf * 2 + w]);
            }
        }
    }
}

// ============================================================================
// Kernel 3: fold partial sums -> scale/shift per (vb, d)
// ============================================================================
__global__ void k_stats2(const float* __restrict__ gamma, const float* __restrict__ beta) {
    int d = blockIdx.x * 256 + threadIdx.x;
    int vb = blockIdx.y;
    size_t i = (size_t)vb * D_OUTF + d;
    float sm = g_psum[i], sq = g_psum2[i];
    float mean = sm * (1.f / VBSZ);
    float var = fmaxf(sq * (1.f / VBSZ) - mean * mean, 0.f);
    float rstd = rsqrtf(var + BN_EPS);
    float sc = rstd * gamma[d];
    g_scale[i] = sc;
    g_shift[i] = beta[d] - mean * sc;
}

// ============================================================================
// Kernel 4: fused BN*prior + sparsemax. 256-thread block = 2 rows
//   (128 threads/row, z[16]/lane). Newton on f(tau)=sum(max(z-tau,0))-1
//   from tau0=max-1, x8 iters (bit-stable from 12 down to 10; margin kept).
// ============================================================================
__global__ void __launch_bounds__(256) k_sparsemax(const float* __restrict__ priors,
                                                   float* __restrict__ out) {
    __shared__ float  s_max[2][4];
    __shared__ float2 s_red[2][2][4];       // [buf][rslot][warp]
    const int tid = threadIdx.x;
    const int rslot = tid >> 7;             // 0/1: which row of this block
    const int t = tid & 127;
    const int wid = t >> 5, lid = tid & 31;
    const int row = blockIdx.x * 2 + rslot;
    const int vb = row >> 8;

    const float4* xv = reinterpret_cast<const float4*>(g_x + (size_t)row * D_OUTF);
    const float4* pv = reinterpret_cast<const float4*>(priors + (size_t)row * D_OUTF);
    const float4* sv = reinterpret_cast<const float4*>(g_scale + (size_t)vb * D_OUTF);
    const float4* hv = reinterpret_cast<const float4*>(g_shift + (size_t)vb * D_OUTF);

    float z[16];
#pragma unroll
    for (int j = 0; j < 4; j++) {
        int c = t + 128 * j;
        float4 x = __ldcs(xv + c);
        float4 p = __ldcs(pv + c);
        float4 sc = sv[c];
        float4 sh = hv[c];
        z[4 * j + 0] = fmaf(x.x, sc.x, sh.x) * p.x;
        z[4 * j + 1] = fmaf(x.y, sc.y, sh.y) * p.y;
        z[4 * j + 2] = fmaf(x.z, sc.z, sh.z) * p.z;
        z[4 * j + 3] = fmaf(x.w, sc.w, sh.w) * p.w;
    }

    float m = z[0];
#pragma unroll
    for (int i = 1; i < 16; i++) m = fmaxf(m, z[i]);
#pragma unroll
    for (int o = 16; o; o >>= 1) m = fmaxf(m, __shfl_xor_sync(0xffffffffu, m, o));
    if (lid == 0) s_max[rslot][wid] = m;
    __syncthreads();
    m = fmaxf(fmaxf(s_max[rslot][0], s_max[rslot][1]),
              fmaxf(s_max[rslot][2], s_max[rslot][3]));

    float tau = m - 1.f;
#pragma unroll 1
    for (int it = 0; it < 8; it++) {
        float S = 0.f, C = 0.f;
#pragma unroll
        for (int i = 0; i < 16; i++) {
            if (z[i] > tau) { S += z[i]; C += 1.f; }
        }
#pragma unroll
        for (int o = 16; o; o >>= 1) {
            S += __shfl_xor_sync(0xffffffffu, S, o);
            C += __shfl_xor_sync(0xffffffffu, C, o);
        }
        if (lid == 0) s_red[it & 1][rslot][wid] = make_float2(S, C);
        __syncthreads();
        float2 r0 = s_red[it & 1][rslot][0], r1 = s_red[it & 1][rslot][1];
        float2 r2 = s_red[it & 1][rslot][2], r3 = s_red[it & 1][rslot][3];
        tau = (r0.x + r1.x + r2.x + r3.x - 1.f) / (r0.y + r1.y + r2.y + r3.y);
    }

    float4* ov = reinterpret_cast<float4*>(out + (size_t)row * D_OUTF);
#pragma unroll
    for (int j = 0; j < 4; j++) {
        int c = t + 128 * j;
        float4 v;
        v.x = fmaxf(z[4 * j + 0] - tau, 0.f);
        v.y = fmaxf(z[4 * j + 1] - tau, 0.f);
        v.z = fmaxf(z[4 * j + 2] - tau, 0.f);
        v.w = fmaxf(z[4 * j + 3] - tau, 0.f);
        __stcs(ov + c, v);
    }
}

// ============================================================================
// Launch
// ============================================================================
extern "C" void kernel_launch(void* const* d_in, const int* in_sizes, int n_in,
                              void* d_out, int out_size) {
    const float* priors = (const float*)d_in[0];   // [32768, 2048]
    const float* feat   = (const float*)d_in[1];   // [32768, 512]
    const float* Wm     = (const float*)d_in[2];   // [2048, 512]
    const float* gamma  = (const float*)d_in[3];   // [2048]
    const float* beta   = (const float*)d_in[4];   // [2048]
    float* out = (float*)d_out;

    cudaFuncSetAttribute(k_gemm, cudaFuncAttributeMaxDynamicSharedMemorySize, GEMM_SMEM);

    // split + zero fused: 17408 blocks cover A+W, 256 more zero psum/psum2
    k_split<<<17664, 256>>>(feat, Wm);
    k_gemm<<<dim3(16, 256), 256, GEMM_SMEM>>>();
    k_stats2<<<dim3(D_OUTF / 256, NVB), 256>>>(gamma, beta);
    k_sparsemax<<<B_ROWS / 2, 256>>>(priors, out);
}

// round 16
// speedup vs baseline: 2.9710x; 1.0403x over previous
#include <cuda_runtime.h>
#include <cuda_bf16.h>
#include <cuda_fp16.h>
#include <cstdint>

// ============================================================================
// Problem constants
// ============================================================================
#define B_ROWS 32768
#define D_INF  512
#define D_OUTF 2048
#define VBSZ   256
#define NVB    (B_ROWS / VBSZ)   // 128
#define BN_EPS 1e-5f

// ============================================================================
// Device scratch (static globals; no cudaMalloc allowed)
// ============================================================================
__device__ __half g_A0[(size_t)B_ROWS * D_INF];   // fp16 of feat
__device__ __half g_W0[(size_t)D_OUTF * D_INF];   // fp16 of W
__device__ float  g_x [(size_t)B_ROWS * D_OUTF];  // GEMM result
__device__ float  g_psum [(size_t)NVB * D_OUTF];  // col sums per vb
__device__ float  g_psum2[(size_t)NVB * D_OUTF];  // col sumsq per vb
__device__ float  g_scale[(size_t)NVB * D_OUTF];  // rstd*gamma
__device__ float  g_shift[(size_t)NVB * D_OUTF];  // beta - mean*rstd*gamma

// ============================================================================
// PTX helpers (base ISA only: cp.async + ldmatrix + mma.sync)
// ============================================================================
__device__ __forceinline__ uint32_t smem_to_u32(const void* p) {
    uint32_t a;
    asm("{ .reg .u64 t; cvta.to.shared.u64 t, %1; cvt.u32.u64 %0, t; }" : "=r"(a) : "l"(p));
    return a;
}

#define CP_ASYNC_16(dst_u32, src_ptr) \
    asm volatile("cp.async.cg.shared.global [%0], [%1], 16;" :: "r"(dst_u32), "l"(src_ptr))
#define CP_ASYNC_COMMIT() asm volatile("cp.async.commit_group;" ::: "memory")
#define CP_ASYNC_WAIT_3() asm volatile("cp.async.wait_group 3;" ::: "memory")

#define LDMATRIX_X4(r0, r1, r2, r3, addr) \
    asm volatile("ldmatrix.sync.aligned.m8n8.x4.shared.b16 {%0,%1,%2,%3}, [%4];" \
                 : "=r"(r0), "=r"(r1), "=r"(r2), "=r"(r3) : "r"(addr))

#define MMA_16816(d, a, b0, b1) \
    asm volatile("mma.sync.aligned.m16n8k16.row.col.f32.f16.f16.f32 " \
                 "{%0,%1,%2,%3}, {%4,%5,%6,%7}, {%8,%9}, {%0,%1,%2,%3};" \
                 : "+f"((d)[0]), "+f"((d)[1]), "+f"((d)[2]), "+f"((d)[3]) \
                 : "r"((a)[0]), "r"((a)[1]), "r"((a)[2]), "r"((a)[3]), "r"(b0), "r"(b1))

#define BAR_SYNC(id, cnt) \
    asm volatile("bar.sync %0, %1;" :: "r"(id), "r"(cnt) : "memory")

// ============================================================================
// Kernel 1: round fp32 A and W -> fp16; tail blocks zero the stats buffers
// ============================================================================
__global__ void k_split(const float* __restrict__ feat, const float* __restrict__ Wm) {
    constexpr int NA4 = B_ROWS * D_INF / 4;   // 4194304
    constexpr int NW4 = D_OUTF * D_INF / 4;   // 262144
    constexpr int NZ4 = NVB * D_OUTF / 4;     // 65536
    int idx = blockIdx.x * blockDim.x + threadIdx.x;
    if (idx < NA4 + NW4) {
        const float* src;
        __half* dst;
        int i;
        if (idx < NA4) { src = feat; dst = g_A0; i = idx; }
        else { src = Wm; dst = g_W0; i = idx - NA4; }
        float4 a = reinterpret_cast<const float4*>(src)[i];
        __half2 h01 = __floats2half2_rn(a.x, a.y);
        __half2 h23 = __floats2half2_rn(a.z, a.w);
        uint2 hv;
        hv.x = *reinterpret_cast<uint32_t*>(&h01);
        hv.y = *reinterpret_cast<uint32_t*>(&h23);
        *reinterpret_cast<uint2*>(dst + (size_t)i * 4) = hv;
    } else if (idx < NA4 + NW4 + NZ4) {
        int i = idx - (NA4 + NW4);
        float4 zz = make_float4(0.f, 0.f, 0.f, 0.f);
        reinterpret_cast<float4*>(g_psum)[i] = zz;
        reinterpret_cast<float4*>(g_psum2)[i] = zz;
    }
}

// ============================================================================
// Kernel 2: GEMM x = A @ W^T, single fp16 term (16 MMAs per kk).
//   CTA 128x128, 256 thr, BK=32, 5-stage cp.async (100KB smem -> 2 CTAs/SM),
//   ONE barrier per k-tile. At the legacy HMMA pipe floor (rt~16/SMSP).
//   Epilogue: streaming store of x + GhostBN partial sums via atomics.
// ============================================================================
#define BK        32
#define ROW_PAD   40                       // fp16 per smem row (80 bytes)
#define TILE_B    (128 * ROW_PAD * 2)      // 10240 bytes per 128x32 tile
#define STAGE_B   (2 * TILE_B)             // A0,W0 = 20480 bytes
#define NSTAGE    5
#define GEMM_SMEM (NSTAGE * STAGE_B)       // 102400 bytes -> 2 CTAs/SM
#define KTILES    (D_INF / BK)             // 16

__device__ __forceinline__ void gemm_load_stage(
    uint32_t smem_base, int stage, int m0, int n0, int k0, int tid)
{
    const __half* bases[2] = {
        g_A0 + (size_t)m0 * D_INF + k0,
        g_W0 + (size_t)n0 * D_INF + k0
    };
    uint32_t sbase = smem_base + stage * STAGE_B;
#pragma unroll
    for (int i = 0; i < 4; i++) {
        int chunk = tid + 256 * i;          // 0..1023
        int tile = chunk >> 9;              // 0..1
        int idx = chunk & 511;
        int row = idx >> 2;
        int seg = idx & 3;
        const __half* src = bases[tile] + (size_t)row * D_INF + seg * 8;
        uint32_t dst = sbase + tile * TILE_B + row * (ROW_PAD * 2) + seg * 16;
        CP_ASYNC_16(dst, src);
    }
}

__global__ void __launch_bounds__(256, 2) k_gemm() {
    extern __shared__ char smem[];
    const uint32_t smem_base = smem_to_u32(smem);
    const int tid = threadIdx.x;
    const int wid = tid >> 5, lid = tid & 31;
    const int m0 = blockIdx.y * 128;
    const int n0 = blockIdx.x * 128;
    const int wm = wid & 1;                 // 0..1 -> m offset 64*wm
    const int wn = wid >> 1;                // 0..3 -> n offset 32*wn

    uint32_t offA[4];
#pragma unroll
    for (int mf = 0; mf < 4; mf++)
        offA[mf] = (uint32_t)((wm * 64 + mf * 16 + (lid & 15)) * (ROW_PAD * 2)
                              + (lid >> 4) * 16);
    uint32_t offB[2];
#pragma unroll
    for (int g = 0; g < 2; g++)
        offB[g] = (uint32_t)((wn * 32 + g * 16 + (lid & 7) + ((lid >> 4) << 3)) * (ROW_PAD * 2)
                             + ((lid >> 3) & 1) * 16);

    float acc[4][4][4];
#pragma unroll
    for (int mf = 0; mf < 4; mf++)
#pragma unroll
        for (int nf = 0; nf < 4; nf++)
#pragma unroll
            for (int r = 0; r < 4; r++) acc[mf][nf][r] = 0.f;

    // Prologue: 4 stages in flight
#pragma unroll
    for (int s = 0; s < 4; s++) {
        gemm_load_stage(smem_base, s, m0, n0, s * BK, tid);
        CP_ASYNC_COMMIT();
    }

    int stage_rd = 0, stage_wr = 4;
    for (int kt = 0; kt < KTILES; kt++) {
        CP_ASYNC_WAIT_3();                  // stage kt landed (<=3 groups pending)
        __syncthreads();                    // single barrier per k-tile

        if (kt + 4 < KTILES)
            gemm_load_stage(smem_base, stage_wr, m0, n0, (kt + 4) * BK, tid);
        CP_ASYNC_COMMIT();
        if (++stage_wr == NSTAGE) stage_wr = 0;

        uint32_t sbase = smem_base + stage_rd * STAGE_B;
        if (++stage_rd == NSTAGE) stage_rd = 0;
        uint32_t sA0 = sbase;
        uint32_t sW0 = sbase + TILE_B;

#pragma unroll
        for (int kk = 0; kk < 2; kk++) {
            uint32_t koff = kk * 32;

            uint32_t b0[2][4];
#pragma unroll
            for (int g = 0; g < 2; g++)
                LDMATRIX_X4(b0[g][0], b0[g][1], b0[g][2], b0[g][3], sW0 + offB[g] + koff);

            uint32_t a0[4][4];
#pragma unroll
            for (int mf = 0; mf < 4; mf++)
                LDMATRIX_X4(a0[mf][0], a0[mf][1], a0[mf][2], a0[mf][3], sA0 + offA[mf] + koff);

#pragma unroll
            for (int mf = 0; mf < 4; mf++)
#pragma unroll
                for (int nf = 0; nf < 4; nf++) {
                    int g = nf >> 1, p = (nf & 1) * 2;
                    MMA_16816(acc[mf][nf], a0[mf], b0[g][p], b0[g][p + 1]);
                }
        }
    }

    // ---- Epilogue: store x (streaming) ----
    const int rbase = m0 + wm * 64 + (lid >> 2);
    const int cbase = n0 + wn * 32 + (lid & 3) * 2;
#pragma unroll
    for (int mf = 0; mf < 4; mf++) {
#pragma unroll
        for (int nf = 0; nf < 4; nf++) {
            int r0 = rbase + mf * 16;
            int c = cbase + nf * 8;
            float2 v0 = make_float2(acc[mf][nf][0], acc[mf][nf][1]);
            float2 v1 = make_float2(acc[mf][nf][2], acc[mf][nf][3]);
            __stcs(reinterpret_cast<float2*>(g_x + (size_t)r0 * D_OUTF + c), v0);
            __stcs(reinterpret_cast<float2*>(g_x + (size_t)(r0 + 8) * D_OUTF + c), v1);
        }
    }

    // ---- Epilogue: GhostBN partial sums (warp: 64 rows x 32 cols; vb = m0>>8)
    float s[8], q[8];
#pragma unroll
    for (int nf = 0; nf < 4; nf++) {
#pragma unroll
        for (int w = 0; w < 2; w++) {
            float ss = 0.f, qq = 0.f;
#pragma unroll
            for (int mf = 0; mf < 4; mf++) {
                float v0 = acc[mf][nf][w], v1 = acc[mf][nf][w + 2];
                ss += v0 + v1;
                qq = fmaf(v0, v0, qq);
                qq = fmaf(v1, v1, qq);
            }
            s[nf * 2 + w] = ss;
            q[nf * 2 + w] = qq;
        }
    }
#pragma unroll
    for (int o = 4; o < 32; o <<= 1) {
#pragma unroll
        for (int t = 0; t < 8; t++) {
            s[t] += __shfl_xor_sync(0xffffffffu, s[t], o);
            q[t] += __shfl_xor_sync(0xffffffffu, q[t], o);
        }
    }
    if ((lid >> 2) == 0) {
        const int vb = m0 >> 8;
        float* ps = g_psum  + (size_t)vb * D_OUTF;
        float* pq = g_psum2 + (size_t)vb * D_OUTF;
#pragma unroll
        for (int nf = 0; nf < 4; nf++) {
#pragma unroll
            for (int w = 0; w < 2; w++) {
                int c = cbase + nf * 8 + w;
                atomicAdd(ps + c, s[nf * 2 + w]);
                atomicAdd(pq + c, q[nf * 2 + w]);
            }
        }
    }
}

// ============================================================================
// Kernel 3: fold partial sums -> scale/shift per (vb, d)
// ============================================================================
__global__ void k_stats2(const float* __restrict__ gamma, const float* __restrict__ beta) {
    int d = blockIdx.x * 256 + threadIdx.x;
    int vb = blockIdx.y;
    size_t i = (size_t)vb * D_OUTF + d;
    float sm = g_psum[i], sq = g_psum2[i];
    float mean = sm * (1.f / VBSZ);
    float var = fmaxf(sq * (1.f / VBSZ) - mean * mean, 0.f);
    float rstd = rsqrtf(var + BN_EPS);
    float sc = rstd * gamma[d];
    g_scale[i] = sc;
    g_shift[i] = beta[d] - mean * sc;
}

// ============================================================================
// Kernel 4: fused BN*prior + sparsemax. 256-thread block = 2 independent rows
//   (128 threads/row, z[16]/lane). NAMED barriers (bar.sync rslot+1, 128)
//   decouple the two rows. Newton on f(tau)=sum(max(z-tau,0))-1 from
//   tau0=max-1, x7 iters (observed convergence <=6, one margin iter).
// ============================================================================
__global__ void __launch_bounds__(256) k_sparsemax(const float* __restrict__ priors,
                                                   float* __restrict__ out) {
    __shared__ float  s_max[2][4];
    __shared__ float2 s_red[2][2][4];       // [buf][rslot][warp-in-row]
    const int tid = threadIdx.x;
    const int rslot = tid >> 7;             // 0/1: which row of this block
    const int t = tid & 127;
    const int wid = t >> 5, lid = tid & 31;
    const int row = blockIdx.x * 2 + rslot;
    const int vb = row >> 8;
    const int barid = rslot + 1;            // named barrier 1 or 2, 128 threads

    const float4* xv = reinterpret_cast<const float4*>(g_x + (size_t)row * D_OUTF);
    const float4* pv = reinterpret_cast<const float4*>(priors + (size_t)row * D_OUTF);
    const float4* sv = reinterpret_cast<const float4*>(g_scale + (size_t)vb * D_OUTF);
    const float4* hv = reinterpret_cast<const float4*>(g_shift + (size_t)vb * D_OUTF);

    float z[16];
#pragma unroll
    for (int j = 0; j < 4; j++) {
        int c = t + 128 * j;
        float4 x = __ldcs(xv + c);
        float4 p = __ldcs(pv + c);
        float4 sc = sv[c];
        float4 sh = hv[c];
        z[4 * j + 0] = fmaf(x.x, sc.x, sh.x) * p.x;
        z[4 * j + 1] = fmaf(x.y, sc.y, sh.y) * p.y;
        z[4 * j + 2] = fmaf(x.z, sc.z, sh.z) * p.z;
        z[4 * j + 3] = fmaf(x.w, sc.w, sh.w) * p.w;
    }

    float m = z[0];
#pragma unroll
    for (int i = 1; i < 16; i++) m = fmaxf(m, z[i]);
#pragma unroll
    for (int o = 16; o; o >>= 1) m = fmaxf(m, __shfl_xor_sync(0xffffffffu, m, o));
    if (lid == 0) s_max[rslot][wid] = m;
    BAR_SYNC(barid, 128);
    m = fmaxf(fmaxf(s_max[rslot][0], s_max[rslot][1]),
              fmaxf(s_max[rslot][2], s_max[rslot][3]));

    float tau = m - 1.f;
#pragma unroll 1
    for (int it = 0; it < 7; it++) {
        float S = 0.f, C = 0.f;
#pragma unroll
        for (int i = 0; i < 16; i++) {
            if (z[i] > tau) { S += z[i]; C += 1.f; }
        }
#pragma unroll
        for (int o = 16; o; o >>= 1) {
            S += __shfl_xor_sync(0xffffffffu, S, o);
            C += __shfl_xor_sync(0xffffffffu, C, o);
        }
        if (lid == 0) s_red[it & 1][rslot][wid] = make_float2(S, C);
        BAR_SYNC(barid, 128);
        float2 r0 = s_red[it & 1][rslot][0], r1 = s_red[it & 1][rslot][1];
        float2 r2 = s_red[it & 1][rslot][2], r3 = s_red[it & 1][rslot][3];
        tau = (r0.x + r1.x + r2.x + r3.x - 1.f) / (r0.y + r1.y + r2.y + r3.y);
    }

    float4* ov = reinterpret_cast<float4*>(out + (size_t)row * D_OUTF);
#pragma unroll
    for (int j = 0; j < 4; j++) {
        int c = t + 128 * j;
        float4 v;
        v.x = fmaxf(z[4 * j + 0] - tau, 0.f);
        v.y = fmaxf(z[4 * j + 1] - tau, 0.f);
        v.z = fmaxf(z[4 * j + 2] - tau, 0.f);
        v.w = fmaxf(z[4 * j + 3] - tau, 0.f);
        __stcs(ov + c, v);
    }
}

// ============================================================================
// Launch
// ============================================================================
extern "C" void kernel_launch(void* const* d_in, const int* in_sizes, int n_in,
                              void* d_out, int out_size) {
    const float* priors = (const float*)d_in[0];   // [32768, 2048]
    const float* feat   = (const float*)d_in[1];   // [32768, 512]
    const float* Wm     = (const float*)d_in[2];   // [2048, 512]
    const float* gamma  = (const float*)d_in[3];   // [2048]
    const float* beta   = (const float*)d_in[4];   // [2048]
    float* out = (float*)d_out;

    cudaFuncSetAttribute(k_gemm, cudaFuncAttributeMaxDynamicSharedMemorySize, GEMM_SMEM);

    // split + zero fused: 17408 blocks cover A+W, 256 more zero psum/psum2
    k_split<<<17664, 256>>>(feat, Wm);
    k_gemm<<<dim3(16, 256), 256, GEMM_SMEM>>>();
    k_stats2<<<dim3(D_OUTF / 256, NVB), 256>>>(gamma, beta);
    k_sparsemax<<<B_ROWS / 2, 256>>>(priors, out);
}